// round 14
// baseline (speedup 1.0000x reference)
#include <cuda_runtime.h>
#include <cuda_bf16.h>
#include <cstdint>

#define Nn 512
#define Bb 8
#define Tt 24
#define BT 192      // B*T
#define Pp 184      // B*(T-1)
#define MX 96       // max nnz per row (actual ~32-55)
#define Dd 16       // Chebyshev degree
#define Ps 64       // Chebyshev sample nodes
#define Rr 6.0f     // fit interval [-R, R]

// ---------------- scratch ----------------
__device__ int   g_nnz[Nn];
__device__ int   g_cols[Nn * MX];
__device__ float g_anorm[Nn * MX];
__device__ float g_vp[8 * Nn];
__device__ float g_wp[8 * Nn];
__device__ float g_M[(size_t)Pp * Dd * Nn];   // M = C^T @ Vs [p][d][j]
__device__ float g_Atv[(size_t)BT * MX * Nn]; // TRANSPOSED [bt][i][n]
__device__ float g_u[BT * Nn];
__device__ float g_s0[BT * Nn];
__device__ float g_s1[BT * Nn];
__device__ float g_Z2[(size_t)BT * Nn * 32];
__device__ float g_H3[(size_t)BT * Nn * 64];
__device__ float g_Fo[Bb * Nn * 128];
__device__ float g_Zh1[Bb * Nn * 32];
__device__ float g_Zh2[Bb * Nn * 16];

// ---------------- fast transcendentals ----------------
__device__ __forceinline__ float fexp(float x) {
    float t = x * 1.4426950408889634f;
    t = fminf(fmaxf(t, -125.0f), 125.0f);
    float fi = floorf(t);
    float fr = t - fi;
    float p = 1.5420358e-4f;
    p = fmaf(p, fr, 1.3333558e-3f);
    p = fmaf(p, fr, 9.6181291e-3f);
    p = fmaf(p, fr, 5.5504109e-2f);
    p = fmaf(p, fr, 2.4022651e-1f);
    p = fmaf(p, fr, 6.9314718e-1f);
    p = fmaf(p, fr, 1.0f);
    return p * __int_as_float(((int)fi + 127) << 23);
}
__device__ __forceinline__ float frcp(float y) {
    float r = __int_as_float((int)(0x7EF311C3u - (unsigned)__float_as_int(y)));
    r = r * (2.0f - y * r);
    r = r * (2.0f - y * r);
    return r;
}
__device__ __forceinline__ float fsig(float x)  { return frcp(1.0f + fexp(-x)); }
__device__ __forceinline__ float ftanh_(float x){ return fmaf(2.0f, fsig(2.0f * x), -1.0f); }
__device__ __forceinline__ float lrelu(float x) { return fmaxf(x, 0.01f * x); }

__device__ __forceinline__ float wred_sum(float v) {
#pragma unroll
    for (int o = 16; o; o >>= 1) v += __shfl_xor_sync(0xffffffffu, v, o);
    return v;
}

// ---------------- K0: sparse pattern ----------------
__global__ void k_build(const float* __restrict__ adj_mask,
                        const float* __restrict__ adj_norm) {
    int warp = threadIdx.x >> 5, lane = threadIdx.x & 31;
    int n = blockIdx.x * 8 + warp;
    int base = 0;
    for (int s = 0; s < 16; s++) {
        int m = s * 32 + lane;
        float v = __ldg(&adj_mask[n * Nn + m]);
        unsigned msk = __ballot_sync(0xffffffffu, v != 0.0f);
        if (v != 0.0f) {
            int pos = base + __popc(msk & ((1u << lane) - 1u));
            if (pos < MX) {
                g_cols[n * MX + pos]  = m;
                g_anorm[n * MX + pos] = __ldg(&adj_norm[n * Nn + m]);
            }
        }
        base += __popc(msk);
    }
    if (lane == 0) g_nnz[n] = (base < MX) ? base : MX;
}

// ---------------- v = Ws @ Wp ----------------
__global__ void k_v8(const float* __restrict__ Ws, const float* __restrict__ Wp) {
    int b = blockIdx.x, j = threadIdx.x;
    float acc = 0.0f;
    for (int ii = 0; ii < 64; ii++) {
        int i = b * 64 + ii;
        acc = fmaf(__ldg(&Ws[i]), __ldg(&Wp[i * Nn + j]), acc);
    }
    g_vp[b * Nn + j] = acc;
}
// ---------------- w = v @ Wa ----------------
__global__ void k_w8(const float* __restrict__ Wa) {
    __shared__ float vsh[Nn];
    int b = blockIdx.x, j = threadIdx.x;
    float v = 0.0f;
#pragma unroll
    for (int k = 0; k < 8; k++) v += g_vp[k * Nn + j];
    vsh[j] = v;
    __syncthreads();
    float acc = 0.0f;
    for (int ii = 0; ii < 64; ii++) {
        int i = b * 64 + ii;
        acc = fmaf(vsh[i], __ldg(&Wa[i * Nn + j]), acc);
    }
    g_wp[b * Nn + j] = acc;
}

// ---------------- K2: At values (recompute, 4 ILP chains) + u + s0/s1 ----------------
__global__ void k_at(const float* __restrict__ x) {
    int bt = blockIdx.x;
    int n  = threadIdx.x;
    __shared__ float fs[Nn], ds[Nn], wsh[Nn];
    const float* f = x + (size_t)bt * Nn;
    float fn = f[n];
    fs[n] = fn;
    float w = 0.0f;
#pragma unroll
    for (int k = 0; k < 8; k++) w += g_wp[k * Nn + n];
    wsh[n] = w;
    __syncthreads();
    int cnt = g_nnz[n];
    const int* cl = g_cols + n * MX;
    float a0 = 0.f, a1 = 0.f, a2 = 0.f, a3 = 0.f;
    int i = 0;
    for (; i + 4 <= cnt; i += 4) {
        float d0 = fn - fs[cl[i]];
        float d1 = fn - fs[cl[i + 1]];
        float d2 = fn - fs[cl[i + 2]];
        float d3 = fn - fs[cl[i + 3]];
        a0 += fexp(-d0 * d0);
        a1 += fexp(-d1 * d1);
        a2 += fexp(-d2 * d2);
        a3 += fexp(-d3 * d3);
    }
    for (; i < cnt; i++) {
        float d0 = fn - fs[cl[i]];
        a0 += fexp(-d0 * d0);
    }
    float dn = rsqrtf((a0 + a1) + (a2 + a3));
    ds[n] = dn;
    __syncthreads();
    float* atp = g_Atv + (size_t)bt * MX * Nn + n;
    float s0a = 0.f, s0b = 0.f, s0c = 0.f, s0d = 0.f;
    float s1a = 0.f, s1b = 0.f, s1c = 0.f, s1d = 0.f;
    float ua = 0.f, ub = 0.f, uc = 0.f, ud = 0.f;
    i = 0;
    for (; i + 4 <= cnt; i += 4) {
        int c0 = cl[i], c1 = cl[i + 1], c2 = cl[i + 2], c3 = cl[i + 3];
        float d0 = fn - fs[c0], d1 = fn - fs[c1], d2 = fn - fs[c2], d3 = fn - fs[c3];
        float at0 = fexp(-d0 * d0) * dn * ds[c0];
        float at1 = fexp(-d1 * d1) * dn * ds[c1];
        float at2 = fexp(-d2 * d2) * dn * ds[c2];
        float at3 = fexp(-d3 * d3) * dn * ds[c3];
        atp[(size_t)i * Nn]       = at0;
        atp[(size_t)(i + 1) * Nn] = at1;
        atp[(size_t)(i + 2) * Nn] = at2;
        atp[(size_t)(i + 3) * Nn] = at3;
        s0a += at0; s0b += at1; s0c += at2; s0d += at3;
        s1a = fmaf(at0, fs[c0], s1a); s1b = fmaf(at1, fs[c1], s1b);
        s1c = fmaf(at2, fs[c2], s1c); s1d = fmaf(at3, fs[c3], s1d);
        ua  = fmaf(wsh[c0], at0, ua); ub  = fmaf(wsh[c1], at1, ub);
        uc  = fmaf(wsh[c2], at2, uc); ud  = fmaf(wsh[c3], at3, ud);
    }
    for (; i < cnt; i++) {
        int c0 = cl[i];
        float d0 = fn - fs[c0];
        float at0 = fexp(-d0 * d0) * dn * ds[c0];
        atp[(size_t)i * Nn] = at0;
        s0a += at0;
        s1a = fmaf(at0, fs[c0], s1a);
        ua  = fmaf(wsh[c0], at0, ua);
    }
    g_u[bt * Nn + n]  = (ua + ub) + (uc + ud);
    g_s0[bt * Nn + n] = (s0a + s0b) + (s0c + s0d);
    g_s1[bt * Nn + n] = (s1a + s1b) + (s1c + s1d);
}

// ---------------- K6: LSTM — 128 thr/block, 16 rows, grid 256 ----------------
__global__ void __launch_bounds__(128) k_lstm(
        const float* __restrict__ x, const float* __restrict__ W_ih,
        const float* __restrict__ W_hh, const float* __restrict__ b_ih,
        const float* __restrict__ b_hh) {
    extern __shared__ float smx[];
    float* whhT = smx;                    // [64][256]
    __shared__ float hsh[16][64];
    int tid = threadIdx.x;                // 128
    for (int i = tid; i < 64 * 256; i += 128) {
        int k = i >> 8, g = i & 255;
        whhT[i] = __ldg(&W_hh[g * 64 + k]);
    }
    int warp = tid >> 5, lane = tid & 31;
    int rbase = warp * 4;
    int row0 = blockIdx.x * 16 + rbase;
    int b = row0 >> 9;
    int n0 = row0 & 511;
    int j0 = lane * 2;

    float2 bi, bf, bg, bo, wii, wif, wig, wio;
    bi.x = __ldg(&b_ih[j0])     + __ldg(&b_hh[j0]);
    bi.y = __ldg(&b_ih[j0 + 1]) + __ldg(&b_hh[j0 + 1]);
    bf.x = __ldg(&b_ih[64 + j0])     + __ldg(&b_hh[64 + j0]);
    bf.y = __ldg(&b_ih[64 + j0 + 1]) + __ldg(&b_hh[64 + j0 + 1]);
    bg.x = __ldg(&b_ih[128 + j0])     + __ldg(&b_hh[128 + j0]);
    bg.y = __ldg(&b_ih[128 + j0 + 1]) + __ldg(&b_hh[128 + j0 + 1]);
    bo.x = __ldg(&b_ih[192 + j0])     + __ldg(&b_hh[192 + j0]);
    bo.y = __ldg(&b_ih[192 + j0 + 1]) + __ldg(&b_hh[192 + j0 + 1]);
    wii = *(const float2*)&W_ih[j0];
    wif = *(const float2*)&W_ih[64 + j0];
    wig = *(const float2*)&W_ih[128 + j0];
    wio = *(const float2*)&W_ih[192 + j0];

    float2 cv[4], hv[4];
#pragma unroll
    for (int r = 0; r < 4; r++) {
        cv[r] = make_float2(0.f, 0.f);
        hv[r] = make_float2(0.f, 0.f);
        *(float2*)&hsh[rbase + r][j0] = hv[r];
    }
    __syncthreads();

    for (int t = 0; t < Tt; t++) {
        float2 gi[4], gf[4], gg[4], go[4];
#pragma unroll
        for (int r = 0; r < 4; r++) {
            float xt = __ldg(&x[(size_t)(b * Tt + t) * Nn + n0 + r]);
            gi[r].x = fmaf(xt, wii.x, bi.x); gi[r].y = fmaf(xt, wii.y, bi.y);
            gf[r].x = fmaf(xt, wif.x, bf.x); gf[r].y = fmaf(xt, wif.y, bf.y);
            gg[r].x = fmaf(xt, wig.x, bg.x); gg[r].y = fmaf(xt, wig.y, bg.y);
            go[r].x = fmaf(xt, wio.x, bo.x); go[r].y = fmaf(xt, wio.y, bo.y);
        }
#pragma unroll 8
        for (int k = 0; k < 64; k++) {
            const float* wr = &whhT[k * 256];
            float2 wi = *(const float2*)&wr[j0];
            float2 wf = *(const float2*)&wr[64 + j0];
            float2 wg = *(const float2*)&wr[128 + j0];
            float2 wo = *(const float2*)&wr[192 + j0];
#pragma unroll
            for (int r = 0; r < 4; r++) {
                float hk = hsh[rbase + r][k];
                gi[r].x = fmaf(hk, wi.x, gi[r].x); gi[r].y = fmaf(hk, wi.y, gi[r].y);
                gf[r].x = fmaf(hk, wf.x, gf[r].x); gf[r].y = fmaf(hk, wf.y, gf[r].y);
                gg[r].x = fmaf(hk, wg.x, gg[r].x); gg[r].y = fmaf(hk, wg.y, gg[r].y);
                go[r].x = fmaf(hk, wo.x, go[r].x); go[r].y = fmaf(hk, wo.y, go[r].y);
            }
        }
#pragma unroll
        for (int r = 0; r < 4; r++) {
            cv[r].x = fsig(gf[r].x) * cv[r].x + fsig(gi[r].x) * ftanh_(gg[r].x);
            cv[r].y = fsig(gf[r].y) * cv[r].y + fsig(gi[r].y) * ftanh_(gg[r].y);
            hv[r].x = fsig(go[r].x) * ftanh_(cv[r].x);
            hv[r].y = fsig(go[r].y) * ftanh_(cv[r].y);
        }
        __syncwarp();
#pragma unroll
        for (int r = 0; r < 4; r++)
            *(float2*)&hsh[rbase + r][j0] = hv[r];
        __syncwarp();
    }
#pragma unroll
    for (int r = 0; r < 4; r++)
        *(float2*)&g_Fo[((size_t)b * Nn + n0 + r) * 128 + 64 + j0] = hv[r];
}

// ---------------- K3 fused: C (smem) + M = C^T @ Vs, one block per p ----------------
__global__ void __launch_bounds__(256) k_cm(const float* __restrict__ Vs) {
    __shared__ float ct[Ps][Dd];      // 4KB
    __shared__ float hh[8][Ps];       // 2KB
    __shared__ float Csm[Nn][Dd];     // 32KB
    __shared__ float Vss[16][128];    // 8KB
    int tid = threadIdx.x, warp = tid >> 5, lane = tid & 31;
    int p = blockIdx.x;
    int b = p / 23, t = p % 23;
    int bt = b * Tt + t;
    for (int i = tid; i < Ps * Dd; i += 256) {
        int s = i >> 4, d = i & 15;
        ct[s][d] = cospif((float)(d * (2 * s + 1)) * (1.0f / (2.0f * Ps)));
    }
    __syncthreads();
    // C phase: warp handles k = warp*64 .. warp*64+63
    for (int kk = 0; kk < 64; kk++) {
        int k = warp * 64 + kk;
        float u = g_u[bt * Nn + k];
        hh[warp][lane]      = fsig(u * Rr * ct[lane][1]);
        hh[warp][lane + 32] = fsig(u * Rr * ct[lane + 32][1]);
        __syncwarp();
        if (lane < Dd) {
            float a0 = 0.f, a1 = 0.f, a2 = 0.f, a3 = 0.f;
#pragma unroll
            for (int s = 0; s < Ps; s += 4) {
                a0 = fmaf(hh[warp][s],     ct[s][lane],     a0);
                a1 = fmaf(hh[warp][s + 1], ct[s + 1][lane], a1);
                a2 = fmaf(hh[warp][s + 2], ct[s + 2][lane], a2);
                a3 = fmaf(hh[warp][s + 3], ct[s + 3][lane], a3);
            }
            float acc = ((a0 + a1) + (a2 + a3)) * (2.0f / Ps);
            if (lane == 0) acc *= 0.5f;
            Csm[k][lane] = acc;
        }
        __syncwarp();
    }
    __syncthreads();
    // GEMM phase: 4 j-tiles of 128
    int ty = tid >> 5, tx = tid & 31;
    for (int jt = 0; jt < 4; jt++) {
        int j0 = jt * 128;
        float acc[2][4];
#pragma unroll
        for (int i = 0; i < 2; i++)
#pragma unroll
            for (int j = 0; j < 4; j++) acc[i][j] = 0.0f;
        for (int k0 = 0; k0 < Nn; k0 += 16) {
            *(float4*)&Vss[ty][tx * 4] =
                *(const float4*)&Vs[(size_t)(k0 + ty) * Nn + j0 + tx * 4];
            *(float4*)&Vss[ty + 8][tx * 4] =
                *(const float4*)&Vs[(size_t)(k0 + ty + 8) * Nn + j0 + tx * 4];
            __syncthreads();
#pragma unroll
            for (int kk = 0; kk < 16; kk++) {
                float a0 = Csm[k0 + kk][ty * 2], a1 = Csm[k0 + kk][ty * 2 + 1];
                float4 b4 = *(float4*)&Vss[kk][tx * 4];
                acc[0][0] = fmaf(a0, b4.x, acc[0][0]); acc[0][1] = fmaf(a0, b4.y, acc[0][1]);
                acc[0][2] = fmaf(a0, b4.z, acc[0][2]); acc[0][3] = fmaf(a0, b4.w, acc[0][3]);
                acc[1][0] = fmaf(a1, b4.x, acc[1][0]); acc[1][1] = fmaf(a1, b4.y, acc[1][1]);
                acc[1][2] = fmaf(a1, b4.z, acc[1][2]); acc[1][3] = fmaf(a1, b4.w, acc[1][3]);
            }
            __syncthreads();
        }
#pragma unroll
        for (int dd = 0; dd < 2; dd++) {
            float4 o = make_float4(acc[dd][0], acc[dd][1], acc[dd][2], acc[dd][3]);
            *(float4*)&g_M[((size_t)p * Dd + ty * 2 + dd) * Nn + j0 + tx * 4] = o;
        }
    }
}

// ---------------- K3c: S rows via Chebyshev, 4 rows per barrier phase ----------------
__global__ void __launch_bounds__(256) k_rows(const float* __restrict__ x) {
    __shared__ float Srow4[4][Nn];
    __shared__ float redsum[4][8], sp0[8], sp1[8];
    int tid = threadIdx.x, warp = tid >> 5, lane = tid & 31;
    int p = blockIdx.y;
    int b = p / 23, t = p % 23;
    int bt = b * Tt + t, bt1 = bt + 1;
    const float* Mp = g_M + (size_t)p * Dd * Nn;
    float m0[Dd], m1[Dd];
#pragma unroll
    for (int d = 0; d < Dd; d++) {
        m0[d] = Mp[(size_t)d * Nn + tid];
        m1[d] = Mp[(size_t)d * Nn + tid + 256];
    }
    const float* fx = x + (size_t)bt * Nn;
    const float* f1 = x + (size_t)bt1 * Nn;
    const float invR = 1.0f / Rr;
    int r4 = tid >> 6, i64 = tid & 63;

    for (int q = 0; q < 8; q++) {
        int mbase = blockIdx.x * 32 + q * 4;
#pragma unroll
        for (int r = 0; r < 4; r++) {
            float a = __ldg(&fx[mbase + r]);
            float tch = fminf(fmaxf(a * invR, -1.0f), 1.0f);
            float Sa = fmaf(m0[1], tch, m0[0]);
            float Sb = fmaf(m1[1], tch, m1[0]);
            float Tp = 1.0f, Tc = tch, t2 = 2.0f * tch;
#pragma unroll
            for (int d = 2; d < Dd; d++) {
                float Tn = fmaf(t2, Tc, -Tp);
                Sa = fmaf(m0[d], Tn, Sa);
                Sb = fmaf(m1[d], Tn, Sb);
                Tp = Tc; Tc = Tn;
            }
            float ea = fexp(Sa), eb = fexp(Sb);
            Srow4[r][tid] = ea; Srow4[r][tid + 256] = eb;
            float ls = wred_sum(ea + eb);
            if (lane == 0) redsum[r][warp] = ls;
        }
        __syncthreads();
        {
            int m = mbase + r4;
            float z = redsum[r4][0];
#pragma unroll
            for (int i = 1; i < 8; i++) z += redsum[r4][i];
            float invz = frcp(z);
            int cnt = g_nnz[m];
            float p0 = 0.0f, p1 = 0.0f;
            for (int i = i64; i < cnt; i += 64) {
                int c = g_cols[m * MX + i];
                float pt = Srow4[r4][c] * invz;
                float av = g_Atv[((size_t)bt1 * MX + i) * Nn + m] * pt;
                p0 += av;
                p1 = fmaf(av, __ldg(&f1[c]), p1);
            }
            p0 = wred_sum(p0);
            p1 = wred_sum(p1);
            if (lane == 0) { sp0[warp] = p0; sp1[warp] = p1; }
        }
        __syncthreads();
        if (i64 == 0) {
            int m = mbase + r4;
            g_s0[bt1 * Nn + m] = sp0[r4 * 2] + sp0[r4 * 2 + 1];
            g_s1[bt1 * Nn + m] = sp1[r4 * 2] + sp1[r4 * 2 + 1];
        }
    }
}

// ---------------- K5a: Z2 = H1@W2+b2, thread-per-row ----------------
__global__ void __launch_bounds__(256) k_z2(const float* __restrict__ W1,
                                            const float* __restrict__ b1,
                                            const float* __restrict__ W2,
                                            const float* __restrict__ b2) {
    __shared__ __align__(16) float w2s[32 * 32];
    __shared__ float w1s[32], b1s[32], b2s[32];
    int tid = threadIdx.x;
    if (tid < 32) { w1s[tid] = W1[tid]; b1s[tid] = b1[tid]; b2s[tid] = b2[tid]; }
    for (int i = tid; i < 1024; i += 256) w2s[i] = W2[i];
    __syncthreads();
    int row = blockIdx.x * 256 + tid;
    float s0 = g_s0[row], s1 = g_s1[row];
    float acc[32];
#pragma unroll
    for (int j = 0; j < 32; j++) acc[j] = b2s[j];
#pragma unroll 4
    for (int h = 0; h < 32; h++) {
        float h1 = lrelu(fmaf(s1, w1s[h], s0 * b1s[h]));
#pragma unroll
        for (int q = 0; q < 8; q++) {
            float4 wv = *(const float4*)&w2s[h * 32 + q * 4];
            acc[q * 4]     = fmaf(h1, wv.x, acc[q * 4]);
            acc[q * 4 + 1] = fmaf(h1, wv.y, acc[q * 4 + 1]);
            acc[q * 4 + 2] = fmaf(h1, wv.z, acc[q * 4 + 2]);
            acc[q * 4 + 3] = fmaf(h1, wv.w, acc[q * 4 + 3]);
        }
    }
    float* zp = &g_Z2[(size_t)row * 32];
#pragma unroll
    for (int q = 0; q < 8; q++) {
        float4 o = make_float4(acc[q * 4], acc[q * 4 + 1], acc[q * 4 + 2], acc[q * 4 + 3]);
        *(float4*)&zp[q * 4] = o;
    }
}

// ---------------- K5bc fused: H2=lrelu(At@Z2); Z3=H2@W3+b3 (smem); H3=lrelu(At@Z3) ----------------
__global__ void __launch_bounds__(512) k_gcn23(const float* __restrict__ W3,
                                               const float* __restrict__ b3) {
    extern __shared__ float sm[];
    float* Z2sh = sm;                   // 512*32
    float* Z3sh = sm + Nn * 32;         // 512*64
    float* w3s  = sm + Nn * 32 + Nn * 64;  // 2048
    int tid = threadIdx.x, warp = tid >> 5, lane = tid & 31;  // 16 warps
    int bt = blockIdx.x;
    for (int i = tid; i < 2048; i += 512) w3s[i] = __ldg(&W3[i]);
    const float4* z2p = (const float4*)(g_Z2 + (size_t)bt * Nn * 32);
    float4* z2s = (float4*)Z2sh;
    for (int i = tid; i < Nn * 8; i += 512) z2s[i] = z2p[i];
    __syncthreads();
    float bz0 = __ldg(&b3[lane]), bz1 = __ldg(&b3[lane + 32]);
    // phase 1: rows warp*32 .. +31 — H2 then Z3 into smem
    for (int rr = 0; rr < 32; rr++) {
        int n = warp * 32 + rr;
        int cnt = g_nnz[n];
        const int* cl = g_cols + n * MX;
        const float* atv = g_Atv + (size_t)bt * MX * Nn + n;
        float a0 = 0.0f, a1 = 0.0f;
        int i = 0;
        for (; i + 2 <= cnt; i += 2) {
            a0 = fmaf(atv[(size_t)i * Nn],       Z2sh[cl[i] * 32 + lane],     a0);
            a1 = fmaf(atv[(size_t)(i + 1) * Nn], Z2sh[cl[i + 1] * 32 + lane], a1);
        }
        if (i < cnt) a0 = fmaf(atv[(size_t)i * Nn], Z2sh[cl[i] * 32 + lane], a0);
        float h2 = lrelu(a0 + a1);
        float z0 = bz0, z1 = bz1;
#pragma unroll
        for (int h = 0; h < 32; h++) {
            float hv = __shfl_sync(0xffffffffu, h2, h);
            z0 = fmaf(hv, w3s[h * 64 + lane], z0);
            z1 = fmaf(hv, w3s[h * 64 + lane + 32], z1);
        }
        Z3sh[n * 64 + lane]      = z0;
        Z3sh[n * 64 + lane + 32] = z1;
    }
    __syncthreads();
    // phase 2: H3 = lrelu(At@Z3sh)
    for (int rr = 0; rr < 32; rr++) {
        int n = warp * 32 + rr;
        int cnt = g_nnz[n];
        const int* cl = g_cols + n * MX;
        const float* atv = g_Atv + (size_t)bt * MX * Nn + n;
        float a0 = 0.0f, a1 = 0.0f, a2 = 0.0f, a3 = 0.0f;
        int i = 0;
        for (; i + 2 <= cnt; i += 2) {
            float av0 = atv[(size_t)i * Nn];
            float av1 = atv[(size_t)(i + 1) * Nn];
            int c0 = cl[i], c1 = cl[i + 1];
            a0 = fmaf(av0, Z3sh[c0 * 64 + lane],      a0);
            a1 = fmaf(av0, Z3sh[c0 * 64 + lane + 32], a1);
            a2 = fmaf(av1, Z3sh[c1 * 64 + lane],      a2);
            a3 = fmaf(av1, Z3sh[c1 * 64 + lane + 32], a3);
        }
        if (i < cnt) {
            float av0 = atv[(size_t)i * Nn];
            int c0 = cl[i];
            a0 = fmaf(av0, Z3sh[c0 * 64 + lane],      a0);
            a1 = fmaf(av0, Z3sh[c0 * 64 + lane + 32], a1);
        }
        g_H3[((size_t)bt * Nn + n) * 64 + lane]      = lrelu(a0 + a2);
        g_H3[((size_t)bt * Nn + n) * 64 + lane + 32] = lrelu(a1 + a3);
    }
}

// ---------------- K5d: Hs = mean_t H3 -> Fo[:, :64] ----------------
__global__ void k_mean() {
    int o = blockIdx.x * 256 + threadIdx.x;
    int b = o >> 15;
    int rem = o & 32767;
    int n = rem >> 6, j = rem & 63;
    float s = 0.0f;
    for (int t = 0; t < Tt; t++)
        s += g_H3[(((size_t)(b * Tt + t) * Nn) + n) * 64 + j];
    g_Fo[((size_t)b * Nn + n) * 128 + j] = s * (1.0f / 24.0f);
}

// ---------------- K7: attention — W_attn/Wh1 smem-staged, 16 rows/block ----------------
__global__ void __launch_bounds__(256) k_attn(const float* __restrict__ W_attn,
                                              const float* __restrict__ b_attn,
                                              const float* __restrict__ Wh1,
                                              const float* __restrict__ bh1) {
    extern __shared__ float sm[];
    float* Wsm  = sm;                 // 128*128
    float* W1sm = sm + 16384;         // 128*32
    __shared__ float fosm[2][128], fasm[2][128], red[2][4], psm[2][4][32];
    __shared__ float basm[128], b1sm[32];
    int tid = threadIdx.x;
    for (int i = tid; i < 16384; i += 256) Wsm[i] = __ldg(&W_attn[i]);
    for (int i = tid; i < 4096; i += 256)  W1sm[i] = __ldg(&Wh1[i]);
    if (tid < 128) basm[tid] = __ldg(&b_attn[tid]);
    if (tid < 32)  b1sm[tid] = __ldg(&bh1[tid]);
    __syncthreads();
    int half = tid >> 7;
    int t2 = tid & 127;
    int lane = tid & 31;
    int w4 = (tid >> 5) & 3;

    for (int rp = 0; rp < 8; rp++) {
        int row = blockIdx.x * 16 + rp * 2 + half;
        float fov = g_Fo[(size_t)row * 128 + t2];
        fosm[half][t2] = fov;
        __syncthreads();
        float acc = basm[t2];
#pragma unroll 8
        for (int i = 0; i < 128; i++)
            acc = fmaf(fosm[half][i], Wsm[i * 128 + t2], acc);
        float e = fexp(ftanh_(acc));
        float s = wred_sum(e);
        if (lane == 0) red[half][w4] = s;
        __syncthreads();
        s = (red[half][0] + red[half][1]) + (red[half][2] + red[half][3]);
        float fa = fov * e * frcp(s);
        fasm[half][t2] = fa;
        __syncthreads();
        float z = 0.0f;
#pragma unroll
        for (int ii = 0; ii < 32; ii++) {
            int i = w4 * 32 + ii;
            z = fmaf(fasm[half][i], W1sm[i * 32 + lane], z);
        }
        psm[half][w4][lane] = z;
        __syncthreads();
        if (w4 == 0) {
            float zz = (psm[half][0][lane] + psm[half][1][lane])
                     + (psm[half][2][lane] + psm[half][3][lane]) + b1sm[lane];
            g_Zh1[(size_t)row * 32 + lane] = zz;
        }
        __syncthreads();
    }
}

// ---------------- K8: Ho1 = lrelu(adj_norm@Zh1); Zh2 = Ho1@Wh2+bh2 ----------------
__global__ void k_ho1(const float* __restrict__ Wh2, const float* __restrict__ bh2) {
    __shared__ float w2s[32 * 16];
    __shared__ float h2s[8][33];
    int tid = threadIdx.x;
    for (int i = tid; i < 512; i += 256) w2s[i] = Wh2[i];
    __syncthreads();
    int warp = tid >> 5, lane = tid & 31;
    int row = blockIdx.x * 8 + warp;
    int b = row >> 9, n = row & 511;
    const int* cl = g_cols + n * MX;
    int cnt = g_nnz[n];
    const float* av = g_anorm + n * MX;
    float acc = 0.0f;
    for (int i = 0; i < cnt; i++) {
        int c = cl[i];
        acc = fmaf(av[i], g_Zh1[((size_t)(b << 9) + c) * 32 + lane], acc);
    }
    h2s[warp][lane] = lrelu(acc);
    __syncwarp();
    if (lane < 16) {
        float z = __ldg(&bh2[lane]);
#pragma unroll
        for (int h = 0; h < 32; h++) z = fmaf(h2s[warp][h], w2s[h * 16 + lane], z);
        g_Zh2[(size_t)row * 16 + lane] = z;
    }
}

// ---------------- K9: Ho = lrelu(adj_norm@Zh2); out = Ho@W_fc+b_fc ----------------
__global__ void k_out(const float* __restrict__ W_fc, const float* __restrict__ b_fc,
                      float* __restrict__ out) {
    __shared__ float hos[8][17];
    int tid = threadIdx.x;
    int warp = tid >> 5, lane = tid & 31;
    int row = blockIdx.x * 8 + warp;
    int b = row >> 9, n = row & 511;
    const int* cl = g_cols + n * MX;
    int cnt = g_nnz[n];
    const float* av = g_anorm + n * MX;
    if (lane < 16) {
        float acc = 0.0f;
        for (int i = 0; i < cnt; i++) {
            int c = cl[i];
            acc = fmaf(av[i], g_Zh2[((size_t)(b << 9) + c) * 16 + lane], acc);
        }
        hos[warp][lane] = lrelu(acc);
    }
    __syncwarp();
    if (lane < 3) {
        float o = __ldg(&b_fc[lane]);
#pragma unroll
        for (int j = 0; j < 16; j++) o = fmaf(hos[warp][j], __ldg(&W_fc[j * 3 + lane]), o);
        out[(size_t)((b * 3 + lane) << 9) + n] = o;
    }
}

// ---------------- launch (single stream) ----------------
extern "C" void kernel_launch(void* const* d_in, const int* in_sizes, int n_in,
                              void* d_out, int out_size) {
    const float* x        = (const float*)d_in[0];
    const float* adj_norm = (const float*)d_in[1];
    const float* adj_mask = (const float*)d_in[2];
    const float* Vs       = (const float*)d_in[3];
    const float* Ws       = (const float*)d_in[4];
    const float* Wp       = (const float*)d_in[5];
    const float* Wa       = (const float*)d_in[6];
    const float* W1       = (const float*)d_in[8];
    const float* b1       = (const float*)d_in[9];
    const float* W2       = (const float*)d_in[10];
    const float* b2       = (const float*)d_in[11];
    const float* W3       = (const float*)d_in[12];
    const float* b3       = (const float*)d_in[13];
    const float* W_ih     = (const float*)d_in[14];
    const float* W_hh     = (const float*)d_in[15];
    const float* b_ih     = (const float*)d_in[16];
    const float* b_hh     = (const float*)d_in[17];
    const float* W_attn   = (const float*)d_in[18];
    const float* b_attn   = (const float*)d_in[19];
    const float* Wh1      = (const float*)d_in[20];
    const float* bh1      = (const float*)d_in[21];
    const float* Wh2      = (const float*)d_in[22];
    const float* bh2      = (const float*)d_in[23];
    const float* W_fc     = (const float*)d_in[24];
    const float* b_fc     = (const float*)d_in[25];
    float* out = (float*)d_out;

    const int GCN_SMEM = (Nn * 32 + Nn * 64 + 2048) * 4;   // 204800 B
    cudaFuncSetAttribute(k_lstm,   cudaFuncAttributeMaxDynamicSharedMemorySize, 65536);
    cudaFuncSetAttribute(k_gcn23,  cudaFuncAttributeMaxDynamicSharedMemorySize, GCN_SMEM);
    cudaFuncSetAttribute(k_attn,   cudaFuncAttributeMaxDynamicSharedMemorySize, 81920);

    k_build<<<64, 256>>>(adj_mask, adj_norm);          // 1
    k_v8<<<8, 512>>>(Ws, Wp);                          // 2
    k_w8<<<8, 512>>>(Wa);                              // 3
    k_at<<<BT, 512>>>(x);                              // 4 (profiled slot)
    k_lstm<<<Bb * Nn / 16, 128, 65536>>>(x, W_ih, W_hh, b_ih, b_hh);
    k_cm<<<Pp, 256>>>(Vs);
    { dim3 g(16, Pp); k_rows<<<g, 256>>>(x); }
    k_z2<<<BT * Nn / 256, 256>>>(W1, b1, W2, b2);
    k_gcn23<<<BT, 512, GCN_SMEM>>>(W3, b3);
    k_mean<<<Bb * Nn * 64 / 256, 256>>>();
    k_attn<<<Bb * Nn / 16, 256, 81920>>>(W_attn, b_attn, Wh1, bh1);
    k_ho1<<<Bb * Nn / 8, 256>>>(Wh2, bh2);
    k_out<<<Bb * Nn / 8, 256>>>(W_fc, b_fc, out);
}

// round 15
// speedup vs baseline: 1.3277x; 1.3277x over previous
#include <cuda_runtime.h>
#include <cuda_bf16.h>
#include <cstdint>

#define Nn 512
#define Bb 8
#define Tt 24
#define BT 192      // B*T
#define Pp 184      // B*(T-1)
#define MX 96       // max nnz per row (actual ~32-55)
#define Dd 16       // Chebyshev degree
#define Ps 64       // Chebyshev sample nodes
#define Rr 6.0f     // fit interval [-R, R]

// ---------------- scratch ----------------
__device__ int   g_nnz[Nn];
__device__ int   g_cols[Nn * MX];
__device__ float g_anorm[Nn * MX];
__device__ float g_vp[8 * Nn];
__device__ float g_wp[8 * Nn];
__device__ float g_C[(size_t)Pp * Nn * Dd];   // Cheb coeffs [p][k][d]
__device__ float g_M[(size_t)Pp * Dd * Nn];   // M = C^T @ Vs [p][d][j]
__device__ float g_Atv[(size_t)BT * MX * Nn]; // TRANSPOSED [bt][i][n]
__device__ float g_u[BT * Nn];
__device__ float g_s0[BT * Nn];
__device__ float g_s1[BT * Nn];
__device__ float g_Z2[(size_t)BT * Nn * 32];
__device__ float g_Z3[(size_t)BT * Nn * 64];
__device__ float g_H3[(size_t)BT * Nn * 64];
__device__ float g_Fo[Bb * Nn * 128];
__device__ float g_Zh1[Bb * Nn * 32];
__device__ float g_Zh2[Bb * Nn * 16];

// ---------------- fast transcendentals ----------------
__device__ __forceinline__ float fexp(float x) {
    float t = x * 1.4426950408889634f;
    t = fminf(fmaxf(t, -125.0f), 125.0f);
    float fi = floorf(t);
    float fr = t - fi;
    float p = 1.5420358e-4f;
    p = fmaf(p, fr, 1.3333558e-3f);
    p = fmaf(p, fr, 9.6181291e-3f);
    p = fmaf(p, fr, 5.5504109e-2f);
    p = fmaf(p, fr, 2.4022651e-1f);
    p = fmaf(p, fr, 6.9314718e-1f);
    p = fmaf(p, fr, 1.0f);
    return p * __int_as_float(((int)fi + 127) << 23);
}
__device__ __forceinline__ float frcp(float y) {
    float r = __int_as_float((int)(0x7EF311C3u - (unsigned)__float_as_int(y)));
    r = r * (2.0f - y * r);
    r = r * (2.0f - y * r);
    return r;
}
__device__ __forceinline__ float fsig(float x)  { return frcp(1.0f + fexp(-x)); }
__device__ __forceinline__ float ftanh_(float x){ return fmaf(2.0f, fsig(2.0f * x), -1.0f); }
__device__ __forceinline__ float lrelu(float x) { return fmaxf(x, 0.01f * x); }

__device__ __forceinline__ float wred_sum(float v) {
#pragma unroll
    for (int o = 16; o; o >>= 1) v += __shfl_xor_sync(0xffffffffu, v, o);
    return v;
}

// ---------------- K0: sparse pattern ----------------
__global__ void k_build(const float* __restrict__ adj_mask,
                        const float* __restrict__ adj_norm) {
    int warp = threadIdx.x >> 5, lane = threadIdx.x & 31;
    int n = blockIdx.x * 8 + warp;
    int base = 0;
    for (int s = 0; s < 16; s++) {
        int m = s * 32 + lane;
        float v = __ldg(&adj_mask[n * Nn + m]);
        unsigned msk = __ballot_sync(0xffffffffu, v != 0.0f);
        if (v != 0.0f) {
            int pos = base + __popc(msk & ((1u << lane) - 1u));
            if (pos < MX) {
                g_cols[n * MX + pos]  = m;
                g_anorm[n * MX + pos] = __ldg(&adj_norm[n * Nn + m]);
            }
        }
        base += __popc(msk);
    }
    if (lane == 0) g_nnz[n] = (base < MX) ? base : MX;
}

// ---------------- v = Ws @ Wp ----------------
__global__ void k_v8(const float* __restrict__ Ws, const float* __restrict__ Wp) {
    int b = blockIdx.x, j = threadIdx.x;
    float acc = 0.0f;
    for (int ii = 0; ii < 64; ii++) {
        int i = b * 64 + ii;
        acc = fmaf(__ldg(&Ws[i]), __ldg(&Wp[i * Nn + j]), acc);
    }
    g_vp[b * Nn + j] = acc;
}
// ---------------- w = v @ Wa ----------------
__global__ void k_w8(const float* __restrict__ Wa) {
    __shared__ float vsh[Nn];
    int b = blockIdx.x, j = threadIdx.x;
    float v = 0.0f;
#pragma unroll
    for (int k = 0; k < 8; k++) v += g_vp[k * Nn + j];
    vsh[j] = v;
    __syncthreads();
    float acc = 0.0f;
    for (int ii = 0; ii < 64; ii++) {
        int i = b * 64 + ii;
        acc = fmaf(vsh[i], __ldg(&Wa[i * Nn + j]), acc);
    }
    g_wp[b * Nn + j] = acc;
}

// ---------------- K2: At values (recompute, 4 ILP chains) + u + s0/s1 ----------------
__global__ void k_at(const float* __restrict__ x) {
    int bt = blockIdx.x;
    int n  = threadIdx.x;
    __shared__ float fs[Nn], ds[Nn], wsh[Nn];
    const float* f = x + (size_t)bt * Nn;
    float fn = f[n];
    fs[n] = fn;
    float w = 0.0f;
#pragma unroll
    for (int k = 0; k < 8; k++) w += g_wp[k * Nn + n];
    wsh[n] = w;
    __syncthreads();
    int cnt = g_nnz[n];
    const int* cl = g_cols + n * MX;
    float a0 = 0.f, a1 = 0.f, a2 = 0.f, a3 = 0.f;
    int i = 0;
    for (; i + 4 <= cnt; i += 4) {
        float d0 = fn - fs[cl[i]];
        float d1 = fn - fs[cl[i + 1]];
        float d2 = fn - fs[cl[i + 2]];
        float d3 = fn - fs[cl[i + 3]];
        a0 += fexp(-d0 * d0);
        a1 += fexp(-d1 * d1);
        a2 += fexp(-d2 * d2);
        a3 += fexp(-d3 * d3);
    }
    for (; i < cnt; i++) {
        float d0 = fn - fs[cl[i]];
        a0 += fexp(-d0 * d0);
    }
    float dn = rsqrtf((a0 + a1) + (a2 + a3));
    ds[n] = dn;
    __syncthreads();
    float* atp = g_Atv + (size_t)bt * MX * Nn + n;
    float s0a = 0.f, s0b = 0.f, s0c = 0.f, s0d = 0.f;
    float s1a = 0.f, s1b = 0.f, s1c = 0.f, s1d = 0.f;
    float ua = 0.f, ub = 0.f, uc = 0.f, ud = 0.f;
    i = 0;
    for (; i + 4 <= cnt; i += 4) {
        int c0 = cl[i], c1 = cl[i + 1], c2 = cl[i + 2], c3 = cl[i + 3];
        float d0 = fn - fs[c0], d1 = fn - fs[c1], d2 = fn - fs[c2], d3 = fn - fs[c3];
        float at0 = fexp(-d0 * d0) * dn * ds[c0];
        float at1 = fexp(-d1 * d1) * dn * ds[c1];
        float at2 = fexp(-d2 * d2) * dn * ds[c2];
        float at3 = fexp(-d3 * d3) * dn * ds[c3];
        atp[(size_t)i * Nn]       = at0;
        atp[(size_t)(i + 1) * Nn] = at1;
        atp[(size_t)(i + 2) * Nn] = at2;
        atp[(size_t)(i + 3) * Nn] = at3;
        s0a += at0; s0b += at1; s0c += at2; s0d += at3;
        s1a = fmaf(at0, fs[c0], s1a); s1b = fmaf(at1, fs[c1], s1b);
        s1c = fmaf(at2, fs[c2], s1c); s1d = fmaf(at3, fs[c3], s1d);
        ua  = fmaf(wsh[c0], at0, ua); ub  = fmaf(wsh[c1], at1, ub);
        uc  = fmaf(wsh[c2], at2, uc); ud  = fmaf(wsh[c3], at3, ud);
    }
    for (; i < cnt; i++) {
        int c0 = cl[i];
        float d0 = fn - fs[c0];
        float at0 = fexp(-d0 * d0) * dn * ds[c0];
        atp[(size_t)i * Nn] = at0;
        s0a += at0;
        s1a = fmaf(at0, fs[c0], s1a);
        ua  = fmaf(wsh[c0], at0, ua);
    }
    g_u[bt * Nn + n]  = (ua + ub) + (uc + ud);
    g_s0[bt * Nn + n] = (s0a + s0b) + (s0c + s0d);
    g_s1[bt * Nn + n] = (s1a + s1b) + (s1c + s1d);
}

// ---------------- K6: LSTM — 128 thr/block, 16 rows, grid 256 ----------------
__global__ void __launch_bounds__(128) k_lstm(
        const float* __restrict__ x, const float* __restrict__ W_ih,
        const float* __restrict__ W_hh, const float* __restrict__ b_ih,
        const float* __restrict__ b_hh) {
    extern __shared__ float smx[];
    float* whhT = smx;                    // [64][256]
    __shared__ float hsh[16][64];
    int tid = threadIdx.x;                // 128
    for (int i = tid; i < 64 * 256; i += 128) {
        int k = i >> 8, g = i & 255;
        whhT[i] = __ldg(&W_hh[g * 64 + k]);
    }
    int warp = tid >> 5, lane = tid & 31;
    int rbase = warp * 4;
    int row0 = blockIdx.x * 16 + rbase;
    int b = row0 >> 9;
    int n0 = row0 & 511;
    int j0 = lane * 2;

    float2 bi, bf, bg, bo, wii, wif, wig, wio;
    bi.x = __ldg(&b_ih[j0])     + __ldg(&b_hh[j0]);
    bi.y = __ldg(&b_ih[j0 + 1]) + __ldg(&b_hh[j0 + 1]);
    bf.x = __ldg(&b_ih[64 + j0])     + __ldg(&b_hh[64 + j0]);
    bf.y = __ldg(&b_ih[64 + j0 + 1]) + __ldg(&b_hh[64 + j0 + 1]);
    bg.x = __ldg(&b_ih[128 + j0])     + __ldg(&b_hh[128 + j0]);
    bg.y = __ldg(&b_ih[128 + j0 + 1]) + __ldg(&b_hh[128 + j0 + 1]);
    bo.x = __ldg(&b_ih[192 + j0])     + __ldg(&b_hh[192 + j0]);
    bo.y = __ldg(&b_ih[192 + j0 + 1]) + __ldg(&b_hh[192 + j0 + 1]);
    wii = *(const float2*)&W_ih[j0];
    wif = *(const float2*)&W_ih[64 + j0];
    wig = *(const float2*)&W_ih[128 + j0];
    wio = *(const float2*)&W_ih[192 + j0];

    float2 cv[4], hv[4];
#pragma unroll
    for (int r = 0; r < 4; r++) {
        cv[r] = make_float2(0.f, 0.f);
        hv[r] = make_float2(0.f, 0.f);
        *(float2*)&hsh[rbase + r][j0] = hv[r];
    }
    __syncthreads();

    for (int t = 0; t < Tt; t++) {
        float2 gi[4], gf[4], gg[4], go[4];
#pragma unroll
        for (int r = 0; r < 4; r++) {
            float xt = __ldg(&x[(size_t)(b * Tt + t) * Nn + n0 + r]);
            gi[r].x = fmaf(xt, wii.x, bi.x); gi[r].y = fmaf(xt, wii.y, bi.y);
            gf[r].x = fmaf(xt, wif.x, bf.x); gf[r].y = fmaf(xt, wif.y, bf.y);
            gg[r].x = fmaf(xt, wig.x, bg.x); gg[r].y = fmaf(xt, wig.y, bg.y);
            go[r].x = fmaf(xt, wio.x, bo.x); go[r].y = fmaf(xt, wio.y, bo.y);
        }
#pragma unroll 8
        for (int k = 0; k < 64; k++) {
            const float* wr = &whhT[k * 256];
            float2 wi = *(const float2*)&wr[j0];
            float2 wf = *(const float2*)&wr[64 + j0];
            float2 wg = *(const float2*)&wr[128 + j0];
            float2 wo = *(const float2*)&wr[192 + j0];
#pragma unroll
            for (int r = 0; r < 4; r++) {
                float hk = hsh[rbase + r][k];
                gi[r].x = fmaf(hk, wi.x, gi[r].x); gi[r].y = fmaf(hk, wi.y, gi[r].y);
                gf[r].x = fmaf(hk, wf.x, gf[r].x); gf[r].y = fmaf(hk, wf.y, gf[r].y);
                gg[r].x = fmaf(hk, wg.x, gg[r].x); gg[r].y = fmaf(hk, wg.y, gg[r].y);
                go[r].x = fmaf(hk, wo.x, go[r].x); go[r].y = fmaf(hk, wo.y, go[r].y);
            }
        }
#pragma unroll
        for (int r = 0; r < 4; r++) {
            cv[r].x = fsig(gf[r].x) * cv[r].x + fsig(gi[r].x) * ftanh_(gg[r].x);
            cv[r].y = fsig(gf[r].y) * cv[r].y + fsig(gi[r].y) * ftanh_(gg[r].y);
            hv[r].x = fsig(go[r].x) * ftanh_(cv[r].x);
            hv[r].y = fsig(go[r].y) * ftanh_(cv[r].y);
        }
        __syncwarp();
#pragma unroll
        for (int r = 0; r < 4; r++)
            *(float2*)&hsh[rbase + r][j0] = hv[r];
        __syncwarp();
    }
#pragma unroll
    for (int r = 0; r < 4; r++)
        *(float2*)&g_Fo[((size_t)b * Nn + n0 + r) * 128 + 64 + j0] = hv[r];
}

// ---------------- K3a: Chebyshev coefficients (Dd=16, cos table inline) ----------------
__global__ void k_coef() {
    __shared__ float ct[Ps][Dd];
    __shared__ float h[8][Ps];
    int tid = threadIdx.x, warp = tid >> 5, lane = tid & 31;
    int p = blockIdx.y;
    int b = p / 23, t = p % 23;
    int bt = b * Tt + t;
    for (int i = tid; i < Ps * Dd; i += 256) {
        int s = i >> 4, d = i & 15;
        ct[s][d] = cospif((float)(d * (2 * s + 1)) * (1.0f / (2.0f * Ps)));
    }
    __syncthreads();
#pragma unroll
    for (int kk = 0; kk < 8; kk++) {
        int k = blockIdx.x * 64 + warp * 8 + kk;
        float u = g_u[bt * Nn + k];
        h[warp][lane]      = fsig(u * Rr * ct[lane][1]);
        h[warp][lane + 32] = fsig(u * Rr * ct[lane + 32][1]);
        __syncwarp();
        if (lane < Dd) {
            float acc = 0.0f;
#pragma unroll
            for (int s = 0; s < Ps; s++) acc = fmaf(h[warp][s], ct[s][lane], acc);
            acc *= (2.0f / Ps);
            if (lane == 0) acc *= 0.5f;
            g_C[((size_t)p * Nn + k) * Dd + lane] = acc;
        }
        __syncwarp();
    }
}

// ---------------- K3b: M[p] = C[p]^T @ Vs (Dd=16 x 128 tile) ----------------
__global__ void __launch_bounds__(256) k_mbuild(const float* __restrict__ Vs) {
    __shared__ float Cs[16][Dd];
    __shared__ float Vss[16][128];
    int tid = threadIdx.x;
    int p = blockIdx.y;
    int j0 = blockIdx.x * 128;
    const float* Cp = g_C + (size_t)p * Nn * Dd;
    int ty = tid >> 5, tx = tid & 31;
    float acc[2][4];
#pragma unroll
    for (int i = 0; i < 2; i++)
#pragma unroll
        for (int j = 0; j < 4; j++) acc[i][j] = 0.0f;

    for (int k0 = 0; k0 < Nn; k0 += 16) {
        Cs[tid >> 4][tid & 15] = Cp[(size_t)(k0 + (tid >> 4)) * Dd + (tid & 15)];
        *(float4*)&Vss[tid >> 5][(tid & 31) * 4] =
            *(const float4*)&Vs[(size_t)(k0 + (tid >> 5)) * Nn + j0 + (tid & 31) * 4];
        *(float4*)&Vss[(tid >> 5) + 8][(tid & 31) * 4] =
            *(const float4*)&Vs[(size_t)(k0 + (tid >> 5) + 8) * Nn + j0 + (tid & 31) * 4];
        __syncthreads();
#pragma unroll
        for (int kk = 0; kk < 16; kk++) {
            float a0 = Cs[kk][ty * 2], a1 = Cs[kk][ty * 2 + 1];
            float4 b4 = *(float4*)&Vss[kk][tx * 4];
            acc[0][0] = fmaf(a0, b4.x, acc[0][0]); acc[0][1] = fmaf(a0, b4.y, acc[0][1]);
            acc[0][2] = fmaf(a0, b4.z, acc[0][2]); acc[0][3] = fmaf(a0, b4.w, acc[0][3]);
            acc[1][0] = fmaf(a1, b4.x, acc[1][0]); acc[1][1] = fmaf(a1, b4.y, acc[1][1]);
            acc[1][2] = fmaf(a1, b4.z, acc[1][2]); acc[1][3] = fmaf(a1, b4.w, acc[1][3]);
        }
        __syncthreads();
    }
#pragma unroll
    for (int dd = 0; dd < 2; dd++) {
        float4 o = make_float4(acc[dd][0], acc[dd][1], acc[dd][2], acc[dd][3]);
        *(float4*)&g_M[((size_t)p * Dd + ty * 2 + dd) * Nn + j0 + tx * 4] = o;
    }
}

// ---------------- K3c v3: S rows, 8 rows/phase, warp-per-row gather ----------------
__global__ void __launch_bounds__(256) k_rows(const float* __restrict__ x) {
    __shared__ float Srow8[8][Nn];        // 16KB
    __shared__ float redsum[8][8];
    int tid = threadIdx.x, warp = tid >> 5, lane = tid & 31;
    int p = blockIdx.y;
    int b = p / 23, t = p % 23;
    int bt = b * Tt + t, bt1 = bt + 1;
    const float* Mp = g_M + (size_t)p * Dd * Nn;
    float m0[Dd], m1[Dd];
#pragma unroll
    for (int d = 0; d < Dd; d++) {
        m0[d] = Mp[(size_t)d * Nn + tid];
        m1[d] = Mp[(size_t)d * Nn + tid + 256];
    }
    const float* fx = x + (size_t)bt * Nn;
    const float* f1 = x + (size_t)bt1 * Nn;
    const float invR = 1.0f / Rr;

    for (int q = 0; q < 4; q++) {
        int mbase = blockIdx.x * 32 + q * 8;
#pragma unroll
        for (int r = 0; r < 8; r++) {
            float a = __ldg(&fx[mbase + r]);
            float tch = fminf(fmaxf(a * invR, -1.0f), 1.0f);
            float Sa = fmaf(m0[1], tch, m0[0]);
            float Sb = fmaf(m1[1], tch, m1[0]);
            float Tp = 1.0f, Tc = tch, t2 = 2.0f * tch;
#pragma unroll
            for (int d = 2; d < Dd; d++) {
                float Tn = fmaf(t2, Tc, -Tp);
                Sa = fmaf(m0[d], Tn, Sa);
                Sb = fmaf(m1[d], Tn, Sb);
                Tp = Tc; Tc = Tn;
            }
            float ea = fexp(Sa), eb = fexp(Sb);   // |S| bounded; no max shift
            Srow8[r][tid] = ea; Srow8[r][tid + 256] = eb;
            float ls = wred_sum(ea + eb);
            if (lane == 0) redsum[r][warp] = ls;
        }
        __syncthreads();
        {
            int m = mbase + warp;                  // warp owns one row
            float zz = (lane < 8) ? redsum[warp][lane] : 0.0f;
            zz = wred_sum(zz);
            float invz = frcp(zz);
            int cnt = g_nnz[m];
            float p0 = 0.0f, p1 = 0.0f;
            for (int i = lane; i < cnt; i += 32) {
                int c = g_cols[m * MX + i];
                float pt = Srow8[warp][c] * invz;
                float av = g_Atv[((size_t)bt1 * MX + i) * Nn + m] * pt;
                p0 += av;
                p1 = fmaf(av, __ldg(&f1[c]), p1);
            }
            p0 = wred_sum(p0);
            p1 = wred_sum(p1);
            if (lane == 0) {
                g_s0[bt1 * Nn + m] = p0;
                g_s1[bt1 * Nn + m] = p1;
            }
        }
        __syncthreads();
    }
}

// ---------------- K5a: Z2 = H1@W2+b2, thread-per-row ----------------
__global__ void __launch_bounds__(256) k_z2(const float* __restrict__ W1,
                                            const float* __restrict__ b1,
                                            const float* __restrict__ W2,
                                            const float* __restrict__ b2) {
    __shared__ __align__(16) float w2s[32 * 32];
    __shared__ float w1s[32], b1s[32], b2s[32];
    int tid = threadIdx.x;
    if (tid < 32) { w1s[tid] = W1[tid]; b1s[tid] = b1[tid]; b2s[tid] = b2[tid]; }
    for (int i = tid; i < 1024; i += 256) w2s[i] = W2[i];
    __syncthreads();
    int row = blockIdx.x * 256 + tid;
    float s0 = g_s0[row], s1 = g_s1[row];
    float acc[32];
#pragma unroll
    for (int j = 0; j < 32; j++) acc[j] = b2s[j];
#pragma unroll 4
    for (int h = 0; h < 32; h++) {
        float h1 = lrelu(fmaf(s1, w1s[h], s0 * b1s[h]));
#pragma unroll
        for (int q = 0; q < 8; q++) {
            float4 wv = *(const float4*)&w2s[h * 32 + q * 4];
            acc[q * 4]     = fmaf(h1, wv.x, acc[q * 4]);
            acc[q * 4 + 1] = fmaf(h1, wv.y, acc[q * 4 + 1]);
            acc[q * 4 + 2] = fmaf(h1, wv.z, acc[q * 4 + 2]);
            acc[q * 4 + 3] = fmaf(h1, wv.w, acc[q * 4 + 3]);
        }
    }
    float* zp = &g_Z2[(size_t)row * 32];
#pragma unroll
    for (int q = 0; q < 8; q++) {
        float4 o = make_float4(acc[q * 4], acc[q * 4 + 1], acc[q * 4 + 2], acc[q * 4 + 3]);
        *(float4*)&zp[q * 4] = o;
    }
}

// ---------------- K5b: H2 = lrelu(At@Z2); Z3 = H2@W3+b3 ----------------
__global__ void k_h2z3(const float* __restrict__ W3, const float* __restrict__ b3) {
    extern __shared__ float Z2sh[];            // 512*32 = 64KB
    __shared__ float w3s[32 * 64];
    int tid = threadIdx.x, warp = tid >> 5, lane = tid & 31;
    int rh = blockIdx.x, bt = blockIdx.y;
    for (int i = tid; i < 2048; i += 256) w3s[i] = __ldg(&W3[i]);
    const float4* z2p = (const float4*)(g_Z2 + (size_t)bt * Nn * 32);
    float4* z2s = (float4*)Z2sh;
    for (int i = tid; i < Nn * 8; i += 256) z2s[i] = z2p[i];
    __syncthreads();
    float bz0 = __ldg(&b3[lane]), bz1 = __ldg(&b3[lane + 32]);
    for (int rr = 0; rr < 32; rr++) {
        int n = rh * 256 + warp * 32 + rr;
        int cnt = g_nnz[n];
        const int* cl = g_cols + n * MX;
        const float* atv = g_Atv + (size_t)bt * MX * Nn + n;
        float a0 = 0.0f, a1 = 0.0f;
        int i = 0;
        for (; i + 2 <= cnt; i += 2) {
            a0 = fmaf(atv[(size_t)i * Nn],       Z2sh[cl[i] * 32 + lane],     a0);
            a1 = fmaf(atv[(size_t)(i + 1) * Nn], Z2sh[cl[i + 1] * 32 + lane], a1);
        }
        if (i < cnt) a0 = fmaf(atv[(size_t)i * Nn], Z2sh[cl[i] * 32 + lane], a0);
        float h2 = lrelu(a0 + a1);
        float z0 = bz0, z1 = bz1;
#pragma unroll
        for (int h = 0; h < 32; h++) {
            float hv = __shfl_sync(0xffffffffu, h2, h);
            z0 = fmaf(hv, w3s[h * 64 + lane], z0);
            z1 = fmaf(hv, w3s[h * 64 + lane + 32], z1);
        }
        g_Z3[((size_t)bt * Nn + n) * 64 + lane]      = z0;
        g_Z3[((size_t)bt * Nn + n) * 64 + lane + 32] = z1;
    }
}

// ---------------- K5c: H3 = lrelu(At@Z3) -> g_H3 ----------------
__global__ void k_h3() {
    extern __shared__ float Z3sh[];            // 512*32 = 64KB
    int tid = threadIdx.x, warp = tid >> 5, lane = tid & 31;
    int jh = blockIdx.x & 1, rh = blockIdx.x >> 1;
    int bt = blockIdx.y;
    const float* z3p = g_Z3 + (size_t)bt * Nn * 64 + jh * 32;
    for (int i = tid; i < Nn * 8; i += 256) {
        int row = i >> 3, c4 = (i & 7) * 4;
        *(float4*)&Z3sh[row * 32 + c4] = *(const float4*)&z3p[(size_t)row * 64 + c4];
    }
    __syncthreads();
    for (int rr = 0; rr < 32; rr++) {
        int n = rh * 256 + warp * 32 + rr;
        int cnt = g_nnz[n];
        const int* cl = g_cols + n * MX;
        const float* atv = g_Atv + (size_t)bt * MX * Nn + n;
        float a0 = 0.0f, a1 = 0.0f;
        int i = 0;
        for (; i + 2 <= cnt; i += 2) {
            a0 = fmaf(atv[(size_t)i * Nn],       Z3sh[cl[i] * 32 + lane],     a0);
            a1 = fmaf(atv[(size_t)(i + 1) * Nn], Z3sh[cl[i + 1] * 32 + lane], a1);
        }
        if (i < cnt) a0 = fmaf(atv[(size_t)i * Nn], Z3sh[cl[i] * 32 + lane], a0);
        g_H3[((size_t)bt * Nn + n) * 64 + jh * 32 + lane] = lrelu(a0 + a1);
    }
}

// ---------------- K5d: Hs = mean_t H3 -> Fo[:, :64] ----------------
__global__ void k_mean() {
    int o = blockIdx.x * 256 + threadIdx.x;
    int b = o >> 15;
    int rem = o & 32767;
    int n = rem >> 6, j = rem & 63;
    float s0 = 0.f, s1 = 0.f, s2 = 0.f, s3 = 0.f;
#pragma unroll
    for (int t = 0; t < Tt; t += 4) {
        s0 += g_H3[(((size_t)(b * Tt + t)     * Nn) + n) * 64 + j];
        s1 += g_H3[(((size_t)(b * Tt + t + 1) * Nn) + n) * 64 + j];
        s2 += g_H3[(((size_t)(b * Tt + t + 2) * Nn) + n) * 64 + j];
        s3 += g_H3[(((size_t)(b * Tt + t + 3) * Nn) + n) * 64 + j];
    }
    g_Fo[((size_t)b * Nn + n) * 128 + j] = ((s0 + s1) + (s2 + s3)) * (1.0f / 24.0f);
}

// ---------------- K7: attention — W_attn/Wh1 smem-staged, 16 rows/block ----------------
__global__ void __launch_bounds__(256) k_attn(const float* __restrict__ W_attn,
                                              const float* __restrict__ b_attn,
                                              const float* __restrict__ Wh1,
                                              const float* __restrict__ bh1) {
    extern __shared__ float sm[];
    float* Wsm  = sm;                 // 128*128
    float* W1sm = sm + 16384;         // 128*32
    __shared__ float fosm[2][128], fasm[2][128], red[2][4], psm[2][4][32];
    __shared__ float basm[128], b1sm[32];
    int tid = threadIdx.x;
    for (int i = tid; i < 16384; i += 256) Wsm[i] = __ldg(&W_attn[i]);
    for (int i = tid; i < 4096; i += 256)  W1sm[i] = __ldg(&Wh1[i]);
    if (tid < 128) basm[tid] = __ldg(&b_attn[tid]);
    if (tid < 32)  b1sm[tid] = __ldg(&bh1[tid]);
    __syncthreads();
    int half = tid >> 7;
    int t2 = tid & 127;
    int lane = tid & 31;
    int w4 = (tid >> 5) & 3;

    for (int rp = 0; rp < 8; rp++) {
        int row = blockIdx.x * 16 + rp * 2 + half;
        float fov = g_Fo[(size_t)row * 128 + t2];
        fosm[half][t2] = fov;
        __syncthreads();
        float acc = basm[t2];
#pragma unroll 8
        for (int i = 0; i < 128; i++)
            acc = fmaf(fosm[half][i], Wsm[i * 128 + t2], acc);
        float e = fexp(ftanh_(acc));
        float s = wred_sum(e);
        if (lane == 0) red[half][w4] = s;
        __syncthreads();
        s = (red[half][0] + red[half][1]) + (red[half][2] + red[half][3]);
        float fa = fov * e * frcp(s);
        fasm[half][t2] = fa;
        __syncthreads();
        float z = 0.0f;
#pragma unroll
        for (int ii = 0; ii < 32; ii++) {
            int i = w4 * 32 + ii;
            z = fmaf(fasm[half][i], W1sm[i * 32 + lane], z);
        }
        psm[half][w4][lane] = z;
        __syncthreads();
        if (w4 == 0) {
            float zz = (psm[half][0][lane] + psm[half][1][lane])
                     + (psm[half][2][lane] + psm[half][3][lane]) + b1sm[lane];
            g_Zh1[(size_t)row * 32 + lane] = zz;
        }
        __syncthreads();
    }
}

// ---------------- K8: Ho1 = lrelu(adj_norm@Zh1); Zh2 = Ho1@Wh2+bh2 ----------------
__global__ void k_ho1(const float* __restrict__ Wh2, const float* __restrict__ bh2) {
    __shared__ float w2s[32 * 16];
    __shared__ float h2s[8][33];
    int tid = threadIdx.x;
    for (int i = tid; i < 512; i += 256) w2s[i] = Wh2[i];
    __syncthreads();
    int warp = tid >> 5, lane = tid & 31;
    int row = blockIdx.x * 8 + warp;
    int b = row >> 9, n = row & 511;
    const int* cl = g_cols + n * MX;
    int cnt = g_nnz[n];
    const float* av = g_anorm + n * MX;
    float acc = 0.0f;
    for (int i = 0; i < cnt; i++) {
        int c = cl[i];
        acc = fmaf(av[i], g_Zh1[((size_t)(b << 9) + c) * 32 + lane], acc);
    }
    h2s[warp][lane] = lrelu(acc);
    __syncwarp();
    if (lane < 16) {
        float z = __ldg(&bh2[lane]);
#pragma unroll
        for (int h = 0; h < 32; h++) z = fmaf(h2s[warp][h], w2s[h * 16 + lane], z);
        g_Zh2[(size_t)row * 16 + lane] = z;
    }
}

// ---------------- K9: Ho = lrelu(adj_norm@Zh2); out = Ho@W_fc+b_fc ----------------
__global__ void k_out(const float* __restrict__ W_fc, const float* __restrict__ b_fc,
                      float* __restrict__ out) {
    __shared__ float hos[8][17];
    int tid = threadIdx.x;
    int warp = tid >> 5, lane = tid & 31;
    int row = blockIdx.x * 8 + warp;
    int b = row >> 9, n = row & 511;
    const int* cl = g_cols + n * MX;
    int cnt = g_nnz[n];
    const float* av = g_anorm + n * MX;
    if (lane < 16) {
        float acc = 0.0f;
        for (int i = 0; i < cnt; i++) {
            int c = cl[i];
            acc = fmaf(av[i], g_Zh2[((size_t)(b << 9) + c) * 16 + lane], acc);
        }
        hos[warp][lane] = lrelu(acc);
    }
    __syncwarp();
    if (lane < 3) {
        float o = __ldg(&b_fc[lane]);
#pragma unroll
        for (int j = 0; j < 16; j++) o = fmaf(hos[warp][j], __ldg(&W_fc[j * 3 + lane]), o);
        out[(size_t)((b * 3 + lane) << 9) + n] = o;
    }
}

// ---------------- launch (single stream) ----------------
extern "C" void kernel_launch(void* const* d_in, const int* in_sizes, int n_in,
                              void* d_out, int out_size) {
    const float* x        = (const float*)d_in[0];
    const float* adj_norm = (const float*)d_in[1];
    const float* adj_mask = (const float*)d_in[2];
    const float* Vs       = (const float*)d_in[3];
    const float* Ws       = (const float*)d_in[4];
    const float* Wp       = (const float*)d_in[5];
    const float* Wa       = (const float*)d_in[6];
    const float* W1       = (const float*)d_in[8];
    const float* b1       = (const float*)d_in[9];
    const float* W2       = (const float*)d_in[10];
    const float* b2       = (const float*)d_in[11];
    const float* W3       = (const float*)d_in[12];
    const float* b3       = (const float*)d_in[13];
    const float* W_ih     = (const float*)d_in[14];
    const float* W_hh     = (const float*)d_in[15];
    const float* b_ih     = (const float*)d_in[16];
    const float* b_hh     = (const float*)d_in[17];
    const float* W_attn   = (const float*)d_in[18];
    const float* b_attn   = (const float*)d_in[19];
    const float* Wh1      = (const float*)d_in[20];
    const float* bh1      = (const float*)d_in[21];
    const float* Wh2      = (const float*)d_in[22];
    const float* bh2      = (const float*)d_in[23];
    const float* W_fc     = (const float*)d_in[24];
    const float* b_fc     = (const float*)d_in[25];
    float* out = (float*)d_out;

    cudaFuncSetAttribute(k_lstm,  cudaFuncAttributeMaxDynamicSharedMemorySize, 65536);
    cudaFuncSetAttribute(k_h2z3,  cudaFuncAttributeMaxDynamicSharedMemorySize, 65536);
    cudaFuncSetAttribute(k_h3,    cudaFuncAttributeMaxDynamicSharedMemorySize, 65536);
    cudaFuncSetAttribute(k_attn,  cudaFuncAttributeMaxDynamicSharedMemorySize, 81920);

    k_build<<<64, 256>>>(adj_mask, adj_norm);          // 1
    k_v8<<<8, 512>>>(Ws, Wp);                          // 2
    k_w8<<<8, 512>>>(Wa);                              // 3
    k_at<<<BT, 512>>>(x);                              // 4 (profiled slot)
    k_lstm<<<Bb * Nn / 16, 128, 65536>>>(x, W_ih, W_hh, b_ih, b_hh);
    { dim3 g(8, Pp);  k_coef<<<g, 256>>>(); }
    { dim3 g(4, Pp);  k_mbuild<<<g, 256>>>(Vs); }
    { dim3 g(16, Pp); k_rows<<<g, 256>>>(x); }
    k_z2<<<BT * Nn / 256, 256>>>(W1, b1, W2, b2);
    { dim3 g(2, BT);  k_h2z3<<<g, 256, Nn * 32 * 4>>>(W3, b3); }
    { dim3 g(4, BT);  k_h3<<<g, 256, Nn * 32 * 4>>>(); }
    k_mean<<<Bb * Nn * 64 / 256, 256>>>();
    k_attn<<<Bb * Nn / 16, 256, 81920>>>(W_attn, b_attn, Wh1, bh1);
    k_ho1<<<Bb * Nn / 8, 256>>>(Wh2, bh2);
    k_out<<<Bb * Nn / 8, 256>>>(W_fc, b_fc, out);
}

// round 16
// speedup vs baseline: 1.3373x; 1.0073x over previous
#include <cuda_runtime.h>
#include <cuda_bf16.h>
#include <cstdint>

#define Nn 512
#define Bb 8
#define Tt 24
#define BT 192      // B*T
#define Pp 184      // B*(T-1)
#define MX 96       // max nnz per row (actual ~32-55)
#define Dd 16       // Chebyshev degree
#define Ps 64       // Chebyshev sample nodes
#define Rr 6.0f     // fit interval [-R, R]

// ---------------- scratch ----------------
__device__ int   g_nnz[Nn];
__device__ int   g_cols[Nn * MX];
__device__ float g_anorm[Nn * MX];
__device__ float g_vp[8 * Nn];
__device__ float g_wp[8 * Nn];
__device__ float g_ds[BT * Nn];               // per-(bt,n) inverse-sqrt degree
__device__ float g_C[(size_t)Pp * Nn * Dd];   // Cheb coeffs [p][k][d]
__device__ float g_M[(size_t)Pp * Dd * Nn];   // M = C^T @ Vs [p][d][j]
__device__ float g_Atv[(size_t)BT * MX * Nn]; // TRANSPOSED [bt][i][n]
__device__ float g_u[BT * Nn];
__device__ float g_s0[BT * Nn];
__device__ float g_s1[BT * Nn];
__device__ float g_Z2[(size_t)BT * Nn * 32];
__device__ float g_Z3[(size_t)BT * Nn * 64];
__device__ float g_H3[(size_t)BT * Nn * 64];
__device__ float g_Fo[Bb * Nn * 128];
__device__ float g_Zh1[Bb * Nn * 32];
__device__ float g_Zh2[Bb * Nn * 16];

// ---------------- fast transcendentals ----------------
__device__ __forceinline__ float fexp(float x) {
    float t = x * 1.4426950408889634f;
    t = fminf(fmaxf(t, -125.0f), 125.0f);
    float fi = floorf(t);
    float fr = t - fi;
    float p = 1.5420358e-4f;
    p = fmaf(p, fr, 1.3333558e-3f);
    p = fmaf(p, fr, 9.6181291e-3f);
    p = fmaf(p, fr, 5.5504109e-2f);
    p = fmaf(p, fr, 2.4022651e-1f);
    p = fmaf(p, fr, 6.9314718e-1f);
    p = fmaf(p, fr, 1.0f);
    return p * __int_as_float(((int)fi + 127) << 23);
}
__device__ __forceinline__ float frcp(float y) {
    float r = __int_as_float((int)(0x7EF311C3u - (unsigned)__float_as_int(y)));
    r = r * (2.0f - y * r);
    r = r * (2.0f - y * r);
    return r;
}
__device__ __forceinline__ float fsig(float x)  { return frcp(1.0f + fexp(-x)); }
__device__ __forceinline__ float ftanh_(float x){ return fmaf(2.0f, fsig(2.0f * x), -1.0f); }
__device__ __forceinline__ float lrelu(float x) { return fmaxf(x, 0.01f * x); }

__device__ __forceinline__ float wred_sum(float v) {
#pragma unroll
    for (int o = 16; o; o >>= 1) v += __shfl_xor_sync(0xffffffffu, v, o);
    return v;
}

// ---------------- K0: sparse pattern ----------------
__global__ void k_build(const float* __restrict__ adj_mask,
                        const float* __restrict__ adj_norm) {
    int warp = threadIdx.x >> 5, lane = threadIdx.x & 31;
    int n = blockIdx.x * 8 + warp;
    int base = 0;
    for (int s = 0; s < 16; s++) {
        int m = s * 32 + lane;
        float v = __ldg(&adj_mask[n * Nn + m]);
        unsigned msk = __ballot_sync(0xffffffffu, v != 0.0f);
        if (v != 0.0f) {
            int pos = base + __popc(msk & ((1u << lane) - 1u));
            if (pos < MX) {
                g_cols[n * MX + pos]  = m;
                g_anorm[n * MX + pos] = __ldg(&adj_norm[n * Nn + m]);
            }
        }
        base += __popc(msk);
    }
    if (lane == 0) g_nnz[n] = (base < MX) ? base : MX;
}

// ---------------- v = Ws @ Wp ----------------
__global__ void k_v8(const float* __restrict__ Ws, const float* __restrict__ Wp) {
    int b = blockIdx.x, j = threadIdx.x;
    float acc = 0.0f;
    for (int ii = 0; ii < 64; ii++) {
        int i = b * 64 + ii;
        acc = fmaf(__ldg(&Ws[i]), __ldg(&Wp[i * Nn + j]), acc);
    }
    g_vp[b * Nn + j] = acc;
}
// ---------------- w = v @ Wa ----------------
__global__ void k_w8(const float* __restrict__ Wa) {
    __shared__ float vsh[Nn];
    int b = blockIdx.x, j = threadIdx.x;
    float v = 0.0f;
#pragma unroll
    for (int k = 0; k < 8; k++) v += g_vp[k * Nn + j];
    vsh[j] = v;
    __syncthreads();
    float acc = 0.0f;
    for (int ii = 0; ii < 64; ii++) {
        int i = b * 64 + ii;
        acc = fmaf(vsh[i], __ldg(&Wa[i * Nn + j]), acc);
    }
    g_wp[b * Nn + j] = acc;
}

// ---------------- K2a: degrees -> g_ds (grid (BT,2), 256 thr) ----------------
__global__ void __launch_bounds__(256) k_deg(const float* __restrict__ x) {
    __shared__ float fs[Nn];
    int bt = blockIdx.x, half = blockIdx.y;
    int tid = threadIdx.x;
    const float* f = x + (size_t)bt * Nn;
    fs[tid]       = __ldg(&f[tid]);
    fs[tid + 256] = __ldg(&f[tid + 256]);
    __syncthreads();
    int n = half * 256 + tid;
    float fn = fs[n];
    int cnt = g_nnz[n];
    const int* cl = g_cols + n * MX;
    float a0 = 0.f, a1 = 0.f, a2 = 0.f, a3 = 0.f;
    int i = 0;
    for (; i + 4 <= cnt; i += 4) {
        float d0 = fn - fs[cl[i]];
        float d1 = fn - fs[cl[i + 1]];
        float d2 = fn - fs[cl[i + 2]];
        float d3 = fn - fs[cl[i + 3]];
        a0 += fexp(-d0 * d0);
        a1 += fexp(-d1 * d1);
        a2 += fexp(-d2 * d2);
        a3 += fexp(-d3 * d3);
    }
    for (; i < cnt; i++) {
        float d0 = fn - fs[cl[i]];
        a0 += fexp(-d0 * d0);
    }
    g_ds[bt * Nn + n] = rsqrtf((a0 + a1) + (a2 + a3));
}

// ---------------- K2b: At values + u + s0/s1 (grid (BT,2), 256 thr) ----------------
__global__ void __launch_bounds__(256) k_atv(const float* __restrict__ x) {
    __shared__ float fs[Nn], ds[Nn], wsh[Nn];
    int bt = blockIdx.x, half = blockIdx.y;
    int tid = threadIdx.x;
    const float* f = x + (size_t)bt * Nn;
#pragma unroll
    for (int s = 0; s < 2; s++) {
        int idx = s * 256 + tid;
        fs[idx] = __ldg(&f[idx]);
        ds[idx] = g_ds[bt * Nn + idx];
        float w = 0.0f;
#pragma unroll
        for (int k = 0; k < 8; k++) w += g_wp[k * Nn + idx];
        wsh[idx] = w;
    }
    __syncthreads();
    int n = half * 256 + tid;
    float fn = fs[n];
    float dn = ds[n];
    int cnt = g_nnz[n];
    const int* cl = g_cols + n * MX;
    float* atp = g_Atv + (size_t)bt * MX * Nn + n;
    float s0a = 0.f, s0b = 0.f, s0c = 0.f, s0d = 0.f;
    float s1a = 0.f, s1b = 0.f, s1c = 0.f, s1d = 0.f;
    float ua = 0.f, ub = 0.f, uc = 0.f, ud = 0.f;
    int i = 0;
    for (; i + 4 <= cnt; i += 4) {
        int c0 = cl[i], c1 = cl[i + 1], c2 = cl[i + 2], c3 = cl[i + 3];
        float d0 = fn - fs[c0], d1 = fn - fs[c1], d2 = fn - fs[c2], d3 = fn - fs[c3];
        float at0 = fexp(-d0 * d0) * dn * ds[c0];
        float at1 = fexp(-d1 * d1) * dn * ds[c1];
        float at2 = fexp(-d2 * d2) * dn * ds[c2];
        float at3 = fexp(-d3 * d3) * dn * ds[c3];
        atp[(size_t)i * Nn]       = at0;
        atp[(size_t)(i + 1) * Nn] = at1;
        atp[(size_t)(i + 2) * Nn] = at2;
        atp[(size_t)(i + 3) * Nn] = at3;
        s0a += at0; s0b += at1; s0c += at2; s0d += at3;
        s1a = fmaf(at0, fs[c0], s1a); s1b = fmaf(at1, fs[c1], s1b);
        s1c = fmaf(at2, fs[c2], s1c); s1d = fmaf(at3, fs[c3], s1d);
        ua  = fmaf(wsh[c0], at0, ua); ub  = fmaf(wsh[c1], at1, ub);
        uc  = fmaf(wsh[c2], at2, uc); ud  = fmaf(wsh[c3], at3, ud);
    }
    for (; i < cnt; i++) {
        int c0 = cl[i];
        float d0 = fn - fs[c0];
        float at0 = fexp(-d0 * d0) * dn * ds[c0];
        atp[(size_t)i * Nn] = at0;
        s0a += at0;
        s1a = fmaf(at0, fs[c0], s1a);
        ua  = fmaf(wsh[c0], at0, ua);
    }
    g_u[bt * Nn + n]  = (ua + ub) + (uc + ud);
    g_s0[bt * Nn + n] = (s0a + s0b) + (s0c + s0d);
    g_s1[bt * Nn + n] = (s1a + s1b) + (s1c + s1d);
}

// ---------------- K6: LSTM — 128 thr/block, 16 rows, grid 256 ----------------
__global__ void __launch_bounds__(128) k_lstm(
        const float* __restrict__ x, const float* __restrict__ W_ih,
        const float* __restrict__ W_hh, const float* __restrict__ b_ih,
        const float* __restrict__ b_hh) {
    extern __shared__ float smx[];
    float* whhT = smx;                    // [64][256]
    __shared__ float hsh[16][64];
    int tid = threadIdx.x;                // 128
    for (int i = tid; i < 64 * 256; i += 128) {
        int k = i >> 8, g = i & 255;
        whhT[i] = __ldg(&W_hh[g * 64 + k]);
    }
    int warp = tid >> 5, lane = tid & 31;
    int rbase = warp * 4;
    int row0 = blockIdx.x * 16 + rbase;
    int b = row0 >> 9;
    int n0 = row0 & 511;
    int j0 = lane * 2;

    float2 bi, bf, bg, bo, wii, wif, wig, wio;
    bi.x = __ldg(&b_ih[j0])     + __ldg(&b_hh[j0]);
    bi.y = __ldg(&b_ih[j0 + 1]) + __ldg(&b_hh[j0 + 1]);
    bf.x = __ldg(&b_ih[64 + j0])     + __ldg(&b_hh[64 + j0]);
    bf.y = __ldg(&b_ih[64 + j0 + 1]) + __ldg(&b_hh[64 + j0 + 1]);
    bg.x = __ldg(&b_ih[128 + j0])     + __ldg(&b_hh[128 + j0]);
    bg.y = __ldg(&b_ih[128 + j0 + 1]) + __ldg(&b_hh[128 + j0 + 1]);
    bo.x = __ldg(&b_ih[192 + j0])     + __ldg(&b_hh[192 + j0]);
    bo.y = __ldg(&b_ih[192 + j0 + 1]) + __ldg(&b_hh[192 + j0 + 1]);
    wii = *(const float2*)&W_ih[j0];
    wif = *(const float2*)&W_ih[64 + j0];
    wig = *(const float2*)&W_ih[128 + j0];
    wio = *(const float2*)&W_ih[192 + j0];

    float2 cv[4], hv[4];
#pragma unroll
    for (int r = 0; r < 4; r++) {
        cv[r] = make_float2(0.f, 0.f);
        hv[r] = make_float2(0.f, 0.f);
        *(float2*)&hsh[rbase + r][j0] = hv[r];
    }
    __syncthreads();

    for (int t = 0; t < Tt; t++) {
        float2 gi[4], gf[4], gg[4], go[4];
#pragma unroll
        for (int r = 0; r < 4; r++) {
            float xt = __ldg(&x[(size_t)(b * Tt + t) * Nn + n0 + r]);
            gi[r].x = fmaf(xt, wii.x, bi.x); gi[r].y = fmaf(xt, wii.y, bi.y);
            gf[r].x = fmaf(xt, wif.x, bf.x); gf[r].y = fmaf(xt, wif.y, bf.y);
            gg[r].x = fmaf(xt, wig.x, bg.x); gg[r].y = fmaf(xt, wig.y, bg.y);
            go[r].x = fmaf(xt, wio.x, bo.x); go[r].y = fmaf(xt, wio.y, bo.y);
        }
#pragma unroll 8
        for (int k = 0; k < 64; k++) {
            const float* wr = &whhT[k * 256];
            float2 wi = *(const float2*)&wr[j0];
            float2 wf = *(const float2*)&wr[64 + j0];
            float2 wg = *(const float2*)&wr[128 + j0];
            float2 wo = *(const float2*)&wr[192 + j0];
#pragma unroll
            for (int r = 0; r < 4; r++) {
                float hk = hsh[rbase + r][k];
                gi[r].x = fmaf(hk, wi.x, gi[r].x); gi[r].y = fmaf(hk, wi.y, gi[r].y);
                gf[r].x = fmaf(hk, wf.x, gf[r].x); gf[r].y = fmaf(hk, wf.y, gf[r].y);
                gg[r].x = fmaf(hk, wg.x, gg[r].x); gg[r].y = fmaf(hk, wg.y, gg[r].y);
                go[r].x = fmaf(hk, wo.x, go[r].x); go[r].y = fmaf(hk, wo.y, go[r].y);
            }
        }
#pragma unroll
        for (int r = 0; r < 4; r++) {
            cv[r].x = fsig(gf[r].x) * cv[r].x + fsig(gi[r].x) * ftanh_(gg[r].x);
            cv[r].y = fsig(gf[r].y) * cv[r].y + fsig(gi[r].y) * ftanh_(gg[r].y);
            hv[r].x = fsig(go[r].x) * ftanh_(cv[r].x);
            hv[r].y = fsig(go[r].y) * ftanh_(cv[r].y);
        }
        __syncwarp();
#pragma unroll
        for (int r = 0; r < 4; r++)
            *(float2*)&hsh[rbase + r][j0] = hv[r];
        __syncwarp();
    }
#pragma unroll
    for (int r = 0; r < 4; r++)
        *(float2*)&g_Fo[((size_t)b * Nn + n0 + r) * 128 + 64 + j0] = hv[r];
}

// ---------------- K3a: Chebyshev coefficients (Dd=16, cos table inline) ----------------
__global__ void k_coef() {
    __shared__ float ct[Ps][Dd];
    __shared__ float h[8][Ps];
    int tid = threadIdx.x, warp = tid >> 5, lane = tid & 31;
    int p = blockIdx.y;
    int b = p / 23, t = p % 23;
    int bt = b * Tt + t;
    for (int i = tid; i < Ps * Dd; i += 256) {
        int s = i >> 4, d = i & 15;
        ct[s][d] = cospif((float)(d * (2 * s + 1)) * (1.0f / (2.0f * Ps)));
    }
    __syncthreads();
#pragma unroll
    for (int kk = 0; kk < 8; kk++) {
        int k = blockIdx.x * 64 + warp * 8 + kk;
        float u = g_u[bt * Nn + k];
        h[warp][lane]      = fsig(u * Rr * ct[lane][1]);
        h[warp][lane + 32] = fsig(u * Rr * ct[lane + 32][1]);
        __syncwarp();
        if (lane < Dd) {
            float acc = 0.0f;
#pragma unroll
            for (int s = 0; s < Ps; s++) acc = fmaf(h[warp][s], ct[s][lane], acc);
            acc *= (2.0f / Ps);
            if (lane == 0) acc *= 0.5f;
            g_C[((size_t)p * Nn + k) * Dd + lane] = acc;
        }
        __syncwarp();
    }
}

// ---------------- K3b: M[p] = C[p]^T @ Vs (Dd=16 x 128 tile) ----------------
__global__ void __launch_bounds__(256) k_mbuild(const float* __restrict__ Vs) {
    __shared__ float Cs[16][Dd];
    __shared__ float Vss[16][128];
    int tid = threadIdx.x;
    int p = blockIdx.y;
    int j0 = blockIdx.x * 128;
    const float* Cp = g_C + (size_t)p * Nn * Dd;
    int ty = tid >> 5, tx = tid & 31;
    float acc[2][4];
#pragma unroll
    for (int i = 0; i < 2; i++)
#pragma unroll
        for (int j = 0; j < 4; j++) acc[i][j] = 0.0f;

    for (int k0 = 0; k0 < Nn; k0 += 16) {
        Cs[tid >> 4][tid & 15] = Cp[(size_t)(k0 + (tid >> 4)) * Dd + (tid & 15)];
        *(float4*)&Vss[tid >> 5][(tid & 31) * 4] =
            *(const float4*)&Vs[(size_t)(k0 + (tid >> 5)) * Nn + j0 + (tid & 31) * 4];
        *(float4*)&Vss[(tid >> 5) + 8][(tid & 31) * 4] =
            *(const float4*)&Vs[(size_t)(k0 + (tid >> 5) + 8) * Nn + j0 + (tid & 31) * 4];
        __syncthreads();
#pragma unroll
        for (int kk = 0; kk < 16; kk++) {
            float a0 = Cs[kk][ty * 2], a1 = Cs[kk][ty * 2 + 1];
            float4 b4 = *(float4*)&Vss[kk][tx * 4];
            acc[0][0] = fmaf(a0, b4.x, acc[0][0]); acc[0][1] = fmaf(a0, b4.y, acc[0][1]);
            acc[0][2] = fmaf(a0, b4.z, acc[0][2]); acc[0][3] = fmaf(a0, b4.w, acc[0][3]);
            acc[1][0] = fmaf(a1, b4.x, acc[1][0]); acc[1][1] = fmaf(a1, b4.y, acc[1][1]);
            acc[1][2] = fmaf(a1, b4.z, acc[1][2]); acc[1][3] = fmaf(a1, b4.w, acc[1][3]);
        }
        __syncthreads();
    }
#pragma unroll
    for (int dd = 0; dd < 2; dd++) {
        float4 o = make_float4(acc[dd][0], acc[dd][1], acc[dd][2], acc[dd][3]);
        *(float4*)&g_M[((size_t)p * Dd + ty * 2 + dd) * Nn + j0 + tx * 4] = o;
    }
}

// ---------------- K3c: S rows, 8 rows/phase, warp-per-row gather (At recomputed) ----------------
__global__ void __launch_bounds__(256) k_rows(const float* __restrict__ x) {
    __shared__ float Srow8[8][Nn];        // 16KB
    __shared__ float redsum[8][8];
    int tid = threadIdx.x, warp = tid >> 5, lane = tid & 31;
    int p = blockIdx.y;
    int b = p / 23, t = p % 23;
    int bt = b * Tt + t, bt1 = bt + 1;
    const float* Mp = g_M + (size_t)p * Dd * Nn;
    float m0[Dd], m1[Dd];
#pragma unroll
    for (int d = 0; d < Dd; d++) {
        m0[d] = Mp[(size_t)d * Nn + tid];
        m1[d] = Mp[(size_t)d * Nn + tid + 256];
    }
    const float* fx = x + (size_t)bt * Nn;
    const float* f1 = x + (size_t)bt1 * Nn;
    const float* ds1 = g_ds + (size_t)bt1 * Nn;
    const float invR = 1.0f / Rr;

    for (int q = 0; q < 4; q++) {
        int mbase = blockIdx.x * 32 + q * 8;
#pragma unroll
        for (int r = 0; r < 8; r++) {
            float a = __ldg(&fx[mbase + r]);
            float tch = fminf(fmaxf(a * invR, -1.0f), 1.0f);
            float Sa = fmaf(m0[1], tch, m0[0]);
            float Sb = fmaf(m1[1], tch, m1[0]);
            float Tp = 1.0f, Tc = tch, t2 = 2.0f * tch;
#pragma unroll
            for (int d = 2; d < Dd; d++) {
                float Tn = fmaf(t2, Tc, -Tp);
                Sa = fmaf(m0[d], Tn, Sa);
                Sb = fmaf(m1[d], Tn, Sb);
                Tp = Tc; Tc = Tn;
            }
            float ea = fexp(Sa), eb = fexp(Sb);   // |S| bounded; no max shift
            Srow8[r][tid] = ea; Srow8[r][tid + 256] = eb;
            float ls = wred_sum(ea + eb);
            if (lane == 0) redsum[r][warp] = ls;
        }
        __syncthreads();
        {
            int m = mbase + warp;                  // warp owns one row
            float zz = (lane < 8) ? redsum[warp][lane] : 0.0f;
            zz = wred_sum(zz);
            float invz = frcp(zz);
            float fm  = __ldg(&f1[m]);             // uniform
            float dsm = __ldg(&ds1[m]);            // uniform
            int cnt = g_nnz[m];
            float p0 = 0.0f, p1 = 0.0f;
            for (int i = lane; i < cnt; i += 32) {
                int c = g_cols[m * MX + i];
                float fc = __ldg(&f1[c]);
                float d = fm - fc;
                float at = fexp(-d * d) * dsm * __ldg(&ds1[c]);
                float av = at * Srow8[warp][c] * invz;
                p0 += av;
                p1 = fmaf(av, fc, p1);
            }
            p0 = wred_sum(p0);
            p1 = wred_sum(p1);
            if (lane == 0) {
                g_s0[bt1 * Nn + m] = p0;
                g_s1[bt1 * Nn + m] = p1;
            }
        }
        __syncthreads();
    }
}

// ---------------- K5a: Z2 = H1@W2+b2, thread-per-row ----------------
__global__ void __launch_bounds__(256) k_z2(const float* __restrict__ W1,
                                            const float* __restrict__ b1,
                                            const float* __restrict__ W2,
                                            const float* __restrict__ b2) {
    __shared__ __align__(16) float w2s[32 * 32];
    __shared__ float w1s[32], b1s[32], b2s[32];
    int tid = threadIdx.x;
    if (tid < 32) { w1s[tid] = W1[tid]; b1s[tid] = b1[tid]; b2s[tid] = b2[tid]; }
    for (int i = tid; i < 1024; i += 256) w2s[i] = W2[i];
    __syncthreads();
    int row = blockIdx.x * 256 + tid;
    float s0 = g_s0[row], s1 = g_s1[row];
    float acc[32];
#pragma unroll
    for (int j = 0; j < 32; j++) acc[j] = b2s[j];
#pragma unroll 4
    for (int h = 0; h < 32; h++) {
        float h1 = lrelu(fmaf(s1, w1s[h], s0 * b1s[h]));
#pragma unroll
        for (int q = 0; q < 8; q++) {
            float4 wv = *(const float4*)&w2s[h * 32 + q * 4];
            acc[q * 4]     = fmaf(h1, wv.x, acc[q * 4]);
            acc[q * 4 + 1] = fmaf(h1, wv.y, acc[q * 4 + 1]);
            acc[q * 4 + 2] = fmaf(h1, wv.z, acc[q * 4 + 2]);
            acc[q * 4 + 3] = fmaf(h1, wv.w, acc[q * 4 + 3]);
        }
    }
    float* zp = &g_Z2[(size_t)row * 32];
#pragma unroll
    for (int q = 0; q < 8; q++) {
        float4 o = make_float4(acc[q * 4], acc[q * 4 + 1], acc[q * 4 + 2], acc[q * 4 + 3]);
        *(float4*)&zp[q * 4] = o;
    }
}

// ---------------- K5b: H2 = lrelu(At@Z2); Z3 = H2@W3+b3 ----------------
__global__ void k_h2z3(const float* __restrict__ W3, const float* __restrict__ b3) {
    extern __shared__ float Z2sh[];            // 512*32 = 64KB
    __shared__ float w3s[32 * 64];
    int tid = threadIdx.x, warp = tid >> 5, lane = tid & 31;
    int rh = blockIdx.x, bt = blockIdx.y;
    for (int i = tid; i < 2048; i += 256) w3s[i] = __ldg(&W3[i]);
    const float4* z2p = (const float4*)(g_Z2 + (size_t)bt * Nn * 32);
    float4* z2s = (float4*)Z2sh;
    for (int i = tid; i < Nn * 8; i += 256) z2s[i] = z2p[i];
    __syncthreads();
    float bz0 = __ldg(&b3[lane]), bz1 = __ldg(&b3[lane + 32]);
    for (int rr = 0; rr < 32; rr++) {
        int n = rh * 256 + warp * 32 + rr;
        int cnt = g_nnz[n];
        const int* cl = g_cols + n * MX;
        const float* atv = g_Atv + (size_t)bt * MX * Nn + n;
        float a0 = 0.0f, a1 = 0.0f;
        int i = 0;
        for (; i + 2 <= cnt; i += 2) {
            a0 = fmaf(atv[(size_t)i * Nn],       Z2sh[cl[i] * 32 + lane],     a0);
            a1 = fmaf(atv[(size_t)(i + 1) * Nn], Z2sh[cl[i + 1] * 32 + lane], a1);
        }
        if (i < cnt) a0 = fmaf(atv[(size_t)i * Nn], Z2sh[cl[i] * 32 + lane], a0);
        float h2 = lrelu(a0 + a1);
        float z0 = bz0, z1 = bz1;
#pragma unroll
        for (int h = 0; h < 32; h++) {
            float hv = __shfl_sync(0xffffffffu, h2, h);
            z0 = fmaf(hv, w3s[h * 64 + lane], z0);
            z1 = fmaf(hv, w3s[h * 64 + lane + 32], z1);
        }
        g_Z3[((size_t)bt * Nn + n) * 64 + lane]      = z0;
        g_Z3[((size_t)bt * Nn + n) * 64 + lane + 32] = z1;
    }
}

// ---------------- K5c: H3 = lrelu(At@Z3) -> g_H3 ----------------
__global__ void k_h3() {
    extern __shared__ float Z3sh[];            // 512*32 = 64KB
    int tid = threadIdx.x, warp = tid >> 5, lane = tid & 31;
    int jh = blockIdx.x & 1, rh = blockIdx.x >> 1;
    int bt = blockIdx.y;
    const float* z3p = g_Z3 + (size_t)bt * Nn * 64 + jh * 32;
    for (int i = tid; i < Nn * 8; i += 256) {
        int row = i >> 3, c4 = (i & 7) * 4;
        *(float4*)&Z3sh[row * 32 + c4] = *(const float4*)&z3p[(size_t)row * 64 + c4];
    }
    __syncthreads();
    for (int rr = 0; rr < 32; rr++) {
        int n = rh * 256 + warp * 32 + rr;
        int cnt = g_nnz[n];
        const int* cl = g_cols + n * MX;
        const float* atv = g_Atv + (size_t)bt * MX * Nn + n;
        float a0 = 0.0f, a1 = 0.0f;
        int i = 0;
        for (; i + 2 <= cnt; i += 2) {
            a0 = fmaf(atv[(size_t)i * Nn],       Z3sh[cl[i] * 32 + lane],     a0);
            a1 = fmaf(atv[(size_t)(i + 1) * Nn], Z3sh[cl[i + 1] * 32 + lane], a1);
        }
        if (i < cnt) a0 = fmaf(atv[(size_t)i * Nn], Z3sh[cl[i] * 32 + lane], a0);
        g_H3[((size_t)bt * Nn + n) * 64 + jh * 32 + lane] = lrelu(a0 + a1);
    }
}

// ---------------- K5d: Hs = mean_t H3 -> Fo[:, :64] ----------------
__global__ void k_mean() {
    int o = blockIdx.x * 256 + threadIdx.x;
    int b = o >> 15;
    int rem = o & 32767;
    int n = rem >> 6, j = rem & 63;
    float s0 = 0.f, s1 = 0.f, s2 = 0.f, s3 = 0.f;
#pragma unroll
    for (int t = 0; t < Tt; t += 4) {
        s0 += g_H3[(((size_t)(b * Tt + t)     * Nn) + n) * 64 + j];
        s1 += g_H3[(((size_t)(b * Tt + t + 1) * Nn) + n) * 64 + j];
        s2 += g_H3[(((size_t)(b * Tt + t + 2) * Nn) + n) * 64 + j];
        s3 += g_H3[(((size_t)(b * Tt + t + 3) * Nn) + n) * 64 + j];
    }
    g_Fo[((size_t)b * Nn + n) * 128 + j] = ((s0 + s1) + (s2 + s3)) * (1.0f / 24.0f);
}

// ---------------- K7: attention — W_attn/Wh1 smem-staged, 16 rows/block ----------------
__global__ void __launch_bounds__(256) k_attn(const float* __restrict__ W_attn,
                                              const float* __restrict__ b_attn,
                                              const float* __restrict__ Wh1,
                                              const float* __restrict__ bh1) {
    extern __shared__ float sm[];
    float* Wsm  = sm;                 // 128*128
    float* W1sm = sm + 16384;         // 128*32
    __shared__ float fosm[2][128], fasm[2][128], red[2][4], psm[2][4][32];
    __shared__ float basm[128], b1sm[32];
    int tid = threadIdx.x;
    for (int i = tid; i < 16384; i += 256) Wsm[i] = __ldg(&W_attn[i]);
    for (int i = tid; i < 4096; i += 256)  W1sm[i] = __ldg(&Wh1[i]);
    if (tid < 128) basm[tid] = __ldg(&b_attn[tid]);
    if (tid < 32)  b1sm[tid] = __ldg(&bh1[tid]);
    __syncthreads();
    int half = tid >> 7;
    int t2 = tid & 127;
    int lane = tid & 31;
    int w4 = (tid >> 5) & 3;

    for (int rp = 0; rp < 8; rp++) {
        int row = blockIdx.x * 16 + rp * 2 + half;
        float fov = g_Fo[(size_t)row * 128 + t2];
        fosm[half][t2] = fov;
        __syncthreads();
        float acc = basm[t2];
#pragma unroll 8
        for (int i = 0; i < 128; i++)
            acc = fmaf(fosm[half][i], Wsm[i * 128 + t2], acc);
        float e = fexp(ftanh_(acc));
        float s = wred_sum(e);
        if (lane == 0) red[half][w4] = s;
        __syncthreads();
        s = (red[half][0] + red[half][1]) + (red[half][2] + red[half][3]);
        float fa = fov * e * frcp(s);
        fasm[half][t2] = fa;
        __syncthreads();
        float z = 0.0f;
#pragma unroll
        for (int ii = 0; ii < 32; ii++) {
            int i = w4 * 32 + ii;
            z = fmaf(fasm[half][i], W1sm[i * 32 + lane], z);
        }
        psm[half][w4][lane] = z;
        __syncthreads();
        if (w4 == 0) {
            float zz = (psm[half][0][lane] + psm[half][1][lane])
                     + (psm[half][2][lane] + psm[half][3][lane]) + b1sm[lane];
            g_Zh1[(size_t)row * 32 + lane] = zz;
        }
        __syncthreads();
    }
}

// ---------------- K8: Ho1 = lrelu(adj_norm@Zh1); Zh2 = Ho1@Wh2+bh2 ----------------
__global__ void k_ho1(const float* __restrict__ Wh2, const float* __restrict__ bh2) {
    __shared__ float w2s[32 * 16];
    __shared__ float h2s[8][33];
    int tid = threadIdx.x;
    for (int i = tid; i < 512; i += 256) w2s[i] = Wh2[i];
    __syncthreads();
    int warp = tid >> 5, lane = tid & 31;
    int row = blockIdx.x * 8 + warp;
    int b = row >> 9, n = row & 511;
    const int* cl = g_cols + n * MX;
    int cnt = g_nnz[n];
    const float* av = g_anorm + n * MX;
    float acc = 0.0f;
    for (int i = 0; i < cnt; i++) {
        int c = cl[i];
        acc = fmaf(av[i], g_Zh1[((size_t)(b << 9) + c) * 32 + lane], acc);
    }
    h2s[warp][lane] = lrelu(acc);
    __syncwarp();
    if (lane < 16) {
        float z = __ldg(&bh2[lane]);
#pragma unroll
        for (int h = 0; h < 32; h++) z = fmaf(h2s[warp][h], w2s[h * 16 + lane], z);
        g_Zh2[(size_t)row * 16 + lane] = z;
    }
}

// ---------------- K9: Ho = lrelu(adj_norm@Zh2); out = Ho@W_fc+b_fc ----------------
__global__ void k_out(const float* __restrict__ W_fc, const float* __restrict__ b_fc,
                      float* __restrict__ out) {
    __shared__ float hos[8][17];
    int tid = threadIdx.x;
    int warp = tid >> 5, lane = tid & 31;
    int row = blockIdx.x * 8 + warp;
    int b = row >> 9, n = row & 511;
    const int* cl = g_cols + n * MX;
    int cnt = g_nnz[n];
    const float* av = g_anorm + n * MX;
    if (lane < 16) {
        float acc = 0.0f;
        for (int i = 0; i < cnt; i++) {
            int c = cl[i];
            acc = fmaf(av[i], g_Zh2[((size_t)(b << 9) + c) * 16 + lane], acc);
        }
        hos[warp][lane] = lrelu(acc);
    }
    __syncwarp();
    if (lane < 3) {
        float o = __ldg(&b_fc[lane]);
#pragma unroll
        for (int j = 0; j < 16; j++) o = fmaf(hos[warp][j], __ldg(&W_fc[j * 3 + lane]), o);
        out[(size_t)((b * 3 + lane) << 9) + n] = o;
    }
}

// ---------------- launch (single stream) ----------------
extern "C" void kernel_launch(void* const* d_in, const int* in_sizes, int n_in,
                              void* d_out, int out_size) {
    const float* x        = (const float*)d_in[0];
    const float* adj_norm = (const float*)d_in[1];
    const float* adj_mask = (const float*)d_in[2];
    const float* Vs       = (const float*)d_in[3];
    const float* Ws       = (const float*)d_in[4];
    const float* Wp       = (const float*)d_in[5];
    const float* Wa       = (const float*)d_in[6];
    const float* W1       = (const float*)d_in[8];
    const float* b1       = (const float*)d_in[9];
    const float* W2       = (const float*)d_in[10];
    const float* b2       = (const float*)d_in[11];
    const float* W3       = (const float*)d_in[12];
    const float* b3       = (const float*)d_in[13];
    const float* W_ih     = (const float*)d_in[14];
    const float* W_hh     = (const float*)d_in[15];
    const float* b_ih     = (const float*)d_in[16];
    const float* b_hh     = (const float*)d_in[17];
    const float* W_attn   = (const float*)d_in[18];
    const float* b_attn   = (const float*)d_in[19];
    const float* Wh1      = (const float*)d_in[20];
    const float* bh1      = (const float*)d_in[21];
    const float* Wh2      = (const float*)d_in[22];
    const float* bh2      = (const float*)d_in[23];
    const float* W_fc     = (const float*)d_in[24];
    const float* b_fc     = (const float*)d_in[25];
    float* out = (float*)d_out;

    cudaFuncSetAttribute(k_lstm,  cudaFuncAttributeMaxDynamicSharedMemorySize, 65536);
    cudaFuncSetAttribute(k_h2z3,  cudaFuncAttributeMaxDynamicSharedMemorySize, 65536);
    cudaFuncSetAttribute(k_h3,    cudaFuncAttributeMaxDynamicSharedMemorySize, 65536);
    cudaFuncSetAttribute(k_attn,  cudaFuncAttributeMaxDynamicSharedMemorySize, 81920);

    k_build<<<64, 256>>>(adj_mask, adj_norm);          // 1
    k_v8<<<8, 512>>>(Ws, Wp);                          // 2
    k_w8<<<8, 512>>>(Wa);                              // 3
    { dim3 g(BT, 2); k_deg<<<g, 256>>>(x); }           // 4 (profiled slot)
    { dim3 g(BT, 2); k_atv<<<g, 256>>>(x); }
    k_lstm<<<Bb * Nn / 16, 128, 65536>>>(x, W_ih, W_hh, b_ih, b_hh);
    { dim3 g(8, Pp);  k_coef<<<g, 256>>>(); }
    { dim3 g(4, Pp);  k_mbuild<<<g, 256>>>(Vs); }
    { dim3 g(16, Pp); k_rows<<<g, 256>>>(x); }
    k_z2<<<BT * Nn / 256, 256>>>(W1, b1, W2, b2);
    { dim3 g(2, BT);  k_h2z3<<<g, 256, Nn * 32 * 4>>>(W3, b3); }
    { dim3 g(4, BT);  k_h3<<<g, 256, Nn * 32 * 4>>>(); }
    k_mean<<<Bb * Nn * 64 / 256, 256>>>();
    k_attn<<<Bb * Nn / 16, 256, 81920>>>(W_attn, b_attn, Wh1, bh1);
    k_ho1<<<Bb * Nn / 8, 256>>>(Wh2, bh2);
    k_out<<<Bb * Nn / 8, 256>>>(W_fc, b_fc, out);
}